// round 8
// baseline (speedup 1.0000x reference)
#include <cuda_runtime.h>
#include <cuda_bf16.h>
#include <cstdint>

#define BB 8
#define LQ 2048
#define LM 2048
#define DD 1024
#define NEGV (-1000000.0f)

// ------------------------- scratch (device globals) -------------------------
__device__ __nv_bfloat16 g_qryhi[(size_t)BB*LQ*DD], g_qrylo[(size_t)BB*LQ*DD];
__device__ __nv_bfloat16 g_Whi[(size_t)DD*DD],      g_Wlo[(size_t)DD*DD];
__device__ __nv_bfloat16 g_qhi[(size_t)BB*LQ*DD],   g_qlo[(size_t)BB*LQ*DD];
__device__ __nv_bfloat16 g_mhi[(size_t)BB*LM*DD],   g_mlo[(size_t)BB*LM*DD];
__device__ __nv_bfloat16 g_mThi[(size_t)BB*DD*LM],  g_mTlo[(size_t)BB*DD*LM];
__device__ float         g_logits[(size_t)BB*LQ*LM];
__device__ __nv_bfloat16 g_whi[(size_t)BB*LQ*LM],   g_wlo[(size_t)BB*LQ*LM];

// ------------------------- helpers -------------------------
__device__ __forceinline__ uint32_t smem_u32(const void* p) {
    uint32_t a;
    asm("{ .reg .u64 t; cvta.to.shared.u64 t, %1; cvt.u32.u64 %0, t; }" : "=r"(a) : "l"(p));
    return a;
}
__device__ __forceinline__ void cp16(uint32_t s, const void* g) {
    asm volatile("cp.async.cg.shared.global [%0], [%1], 16;" :: "r"(s), "l"(g));
}
__device__ __forceinline__ void ldmx4(uint32_t* r, uint32_t a) {
    asm volatile("ldmatrix.sync.aligned.m8n8.x4.shared.b16 {%0,%1,%2,%3}, [%4];"
                 : "=r"(r[0]), "=r"(r[1]), "=r"(r[2]), "=r"(r[3]) : "r"(a));
}
__device__ __forceinline__ void mma16816(float* c, const uint32_t* a, uint32_t b0, uint32_t b1) {
    asm volatile(
        "mma.sync.aligned.m16n8k16.row.col.f32.bf16.bf16.f32 "
        "{%0,%1,%2,%3}, {%4,%5,%6,%7}, {%8,%9}, {%0,%1,%2,%3};"
        : "+f"(c[0]), "+f"(c[1]), "+f"(c[2]), "+f"(c[3])
        : "r"(a[0]), "r"(a[1]), "r"(a[2]), "r"(a[3]), "r"(b0), "r"(b1));
}
__device__ __forceinline__ void split2(float v, __nv_bfloat16& h, __nv_bfloat16& l) {
    h = __float2bfloat16(v);
    l = __float2bfloat16(v - __bfloat162float(h));
}

// ------------------------- split-bf16 mma.sync GEMM (NT, K-major) -------------------------
// C[M,N] = (Ahi+Alo)[M,K]*(Bhi+Blo)[N,K]^T, 3 MMA terms, fp32 accum.
// CTA tile 128(M) x 256(N), 512 threads = 16 warps (2x8), warp tile 64x32.
// K-chunk 64 (one 128B SMEM row per M/N row per chunk), XOR-swizzled, 2 stages.
// EPI: 1 = +bias -> split bf16 ; 2 = +mask NEG -> fp32 ; 3 = plain -> fp32.

#define ROWB 128
#define ATILEB (128 * ROWB)            // 16384
#define BTILEB (256 * ROWB)            // 32768
#define STAGEB (2*ATILEB + 2*BTILEB)   // 98304
#define NSTAGE 2

// Coalesced + swizzled loader: 8 lanes cover one 128B row; chunk' = chunk ^ (row&7).
__device__ __forceinline__ void load_tileA(uint32_t st, const __nv_bfloat16* g, int K, int k0, int tid) {
    #pragma unroll
    for (int p = 0; p < 2; p++) {
        int idx = p * 512 + tid;          // 0..1023
        int row = idx >> 3, c = idx & 7;
        cp16(st + (uint32_t)row * ROWB + (uint32_t)((c ^ (row & 7)) << 4),
             g + (size_t)row * K + k0 + c * 8);
    }
}
__device__ __forceinline__ void load_tileB(uint32_t st, const __nv_bfloat16* g, int K, int k0, int tid) {
    #pragma unroll
    for (int p = 0; p < 4; p++) {
        int idx = p * 512 + tid;          // 0..2047
        int row = idx >> 3, c = idx & 7;
        cp16(st + (uint32_t)row * ROWB + (uint32_t)((c ^ (row & 7)) << 4),
             g + (size_t)row * K + k0 + c * 8);
    }
}

template<int EPI>
__global__ __launch_bounds__(512)
void gemm_mma(const __nv_bfloat16* __restrict__ Ahi, const __nv_bfloat16* __restrict__ Alo,
              const __nv_bfloat16* __restrict__ Bhi, const __nv_bfloat16* __restrict__ Blo,
              const float* __restrict__ bias, const int* __restrict__ mask,
              float* __restrict__ Cf,
              __nv_bfloat16* __restrict__ Chi, __nv_bfloat16* __restrict__ Clo,
              int N, int K, size_t sA, size_t sB, size_t sC)
{
    extern __shared__ __align__(128) char dynsmem[];
    const int tid  = threadIdx.x;
    const int bz   = blockIdx.z;
    const int bm   = blockIdx.y * 128;
    const int bn   = blockIdx.x * 256;
    const int wid  = tid >> 5;
    const int lane = tid & 31;
    const int wm   = (wid >> 3) * 64;     // 0, 64
    const int wn   = (wid & 7) * 32;      // 0..224

    const uint32_t sb = smem_u32(dynsmem);

    const __nv_bfloat16* pAh = Ahi + (size_t)bz * sA + (size_t)bm * K;
    const __nv_bfloat16* pAl = Alo + (size_t)bz * sA + (size_t)bm * K;
    const __nv_bfloat16* pBh = Bhi + (size_t)bz * sB + (size_t)bn * K;
    const __nv_bfloat16* pBl = Blo + (size_t)bz * sB + (size_t)bn * K;

    float acc[4][4][4];
    #pragma unroll
    for (int i = 0; i < 4; i++)
        #pragma unroll
        for (int j = 0; j < 4; j++)
            #pragma unroll
            for (int r = 0; r < 4; r++) acc[i][j][r] = 0.0f;

    const int nk = K >> 6;   // 64-wide k-chunks

    // prologue: stage 0
    {
        load_tileA(sb,                     pAh, K, 0, tid);
        load_tileA(sb + ATILEB,            pAl, K, 0, tid);
        load_tileB(sb + 2*ATILEB,          pBh, K, 0, tid);
        load_tileB(sb + 2*ATILEB + BTILEB, pBl, K, 0, tid);
        asm volatile("cp.async.commit_group;" ::: "memory");
    }

    // ldmatrix per-thread addressing:
    //   row-in-tile = (tileoff) + mtile*16 + (lane&15); tileoffs are multiples of 8,
    //   so xor key = lane&7 (constant). chunk = kk*2 + (lane>>4).
    const uint32_t rowoff = (uint32_t)(lane & 15) * ROWB;
    const int      key    = lane & 7;
    const int      cbase  = lane >> 4;

    for (int c = 0; c < nk; ++c) {
        asm volatile("cp.async.wait_group 0;" ::: "memory");
        __syncthreads();

        if (c + 1 < nk) {
            uint32_t st = sb + (uint32_t)((c + 1) & 1) * STAGEB;
            int k0 = (c + 1) << 6;
            load_tileA(st,                     pAh, K, k0, tid);
            load_tileA(st + ATILEB,            pAl, K, k0, tid);
            load_tileB(st + 2*ATILEB,          pBh, K, k0, tid);
            load_tileB(st + 2*ATILEB + BTILEB, pBl, K, k0, tid);
            asm volatile("cp.async.commit_group;" ::: "memory");
        }

        const uint32_t st = sb + (uint32_t)(c & 1) * STAGEB;
        const uint32_t aH = st + (uint32_t)wm * ROWB + rowoff;
        const uint32_t aL = aH + ATILEB;
        const uint32_t bH = st + 2*ATILEB + (uint32_t)wn * ROWB + rowoff;
        const uint32_t bL = bH + BTILEB;

        #pragma unroll
        for (int kk = 0; kk < 4; kk++) {
            const uint32_t sw = (uint32_t)(((kk*2 + cbase) ^ key) << 4);
            uint32_t bh[2][4], bl[2][4];
            #pragma unroll
            for (int h = 0; h < 2; h++) {
                ldmx4(bh[h], bH + (uint32_t)h * (16 * ROWB) + sw);
                ldmx4(bl[h], bL + (uint32_t)h * (16 * ROWB) + sw);
            }
            #pragma unroll
            for (int mp = 0; mp < 2; mp++) {
                uint32_t ah[2][4], al[2][4];
                #pragma unroll
                for (int m2 = 0; m2 < 2; m2++) {
                    ldmx4(ah[m2], aH + (uint32_t)(mp*2 + m2) * (16 * ROWB) + sw);
                    ldmx4(al[m2], aL + (uint32_t)(mp*2 + m2) * (16 * ROWB) + sw);
                }
                #pragma unroll
                for (int m2 = 0; m2 < 2; m2++) {
                    const int mt = mp*2 + m2;
                    #pragma unroll
                    for (int nt = 0; nt < 4; nt++) {
                        const int g = nt >> 1, s = nt & 1;
                        mma16816(acc[mt][nt], ah[m2], bh[g][s], bh[g][s + 2]);
                        mma16816(acc[mt][nt], al[m2], bh[g][s], bh[g][s + 2]);
                        mma16816(acc[mt][nt], ah[m2], bl[g][s], bl[g][s + 2]);
                    }
                }
            }
        }
    }

    // ---------------- epilogue ----------------
    const int r0 = lane >> 2;
    const int c0 = (lane & 3) * 2;

    #pragma unroll
    for (int mt = 0; mt < 4; mt++) {
        #pragma unroll
        for (int half = 0; half < 2; half++) {
            const size_t grow = (size_t)(bm + wm + mt * 16 + r0 + half * 8);
            #pragma unroll
            for (int nt = 0; nt < 4; nt++) {
                const int gcol = bn + wn + nt * 8 + c0;
                float v0 = acc[mt][nt][half * 2 + 0];
                float v1 = acc[mt][nt][half * 2 + 1];

                if (EPI == 1) {
                    v0 += bias[gcol];
                    v1 += bias[gcol + 1];
                    __nv_bfloat16 h0, l0, h1, l1;
                    split2(v0, h0, l0); split2(v1, h1, l1);
                    uint32_t ph = ((uint32_t)__bfloat16_as_ushort(h1) << 16) | __bfloat16_as_ushort(h0);
                    uint32_t pl = ((uint32_t)__bfloat16_as_ushort(l1) << 16) | __bfloat16_as_ushort(l0);
                    *(uint32_t*)(Chi + (size_t)bz * sC + grow * N + gcol) = ph;
                    *(uint32_t*)(Clo + (size_t)bz * sC + grow * N + gcol) = pl;
                } else if (EPI == 2) {
                    int2 mm = *(const int2*)(mask + (size_t)bz * sC + grow * N + gcol);
                    float2 vv;
                    vv.x = v0 + (mm.x ? 0.0f : NEGV);
                    vv.y = v1 + (mm.y ? 0.0f : NEGV);
                    *(float2*)(Cf + (size_t)bz * sC + grow * N + gcol) = vv;
                } else {
                    *(float2*)(Cf + (size_t)bz * sC + grow * N + gcol) = make_float2(v0, v1);
                }
            }
        }
    }
}

// ------------------------- elementwise split fp32 -> (hi,lo) bf16 -------------------------
__global__ __launch_bounds__(256)
void split_kernel(const float* __restrict__ x, __nv_bfloat16* __restrict__ hi,
                  __nv_bfloat16* __restrict__ lo, size_t n)
{
    size_t i = ((size_t)blockIdx.x * 256 + threadIdx.x) * 4;
    if (i >= n) return;
    float4 v = *(const float4*)(x + i);
    float f[4] = {v.x, v.y, v.z, v.w};
    uint32_t ph[2], pl[2];
    #pragma unroll
    for (int j = 0; j < 2; j++) {
        __nv_bfloat16 h0, l0, h1, l1;
        split2(f[2*j], h0, l0); split2(f[2*j+1], h1, l1);
        ph[j] = ((uint32_t)__bfloat16_as_ushort(h1) << 16) | __bfloat16_as_ushort(h0);
        pl[j] = ((uint32_t)__bfloat16_as_ushort(l1) << 16) | __bfloat16_as_ushort(l0);
    }
    *(uint2*)(hi + i) = make_uint2(ph[0], ph[1]);
    *(uint2*)(lo + i) = make_uint2(pl[0], pl[1]);
}

// ---------------- fused: memories fp32 -> split row-major AND split transposed ----------------
__global__ __launch_bounds__(256)
void split_transpose_kernel(const float* __restrict__ src,
                            __nv_bfloat16* __restrict__ hi, __nv_bfloat16* __restrict__ lo,
                            __nv_bfloat16* __restrict__ thi, __nv_bfloat16* __restrict__ tlo,
                            int R, int C)
{
    __shared__ float t[32][33];
    const int z = blockIdx.z;
    src += (size_t)z * R * C;
    hi  += (size_t)z * R * C;  lo  += (size_t)z * R * C;
    thi += (size_t)z * R * C;  tlo += (size_t)z * R * C;
    const int c0 = blockIdx.x * 32, r0 = blockIdx.y * 32;
    const int tx = threadIdx.x, ty = threadIdx.y;

    #pragma unroll
    for (int i = 0; i < 4; i++) {
        const int r = r0 + ty + 8*i;
        float v = src[(size_t)r * C + c0 + tx];
        t[ty + 8*i][tx] = v;
        __nv_bfloat16 h, l;
        split2(v, h, l);
        hi[(size_t)r * C + c0 + tx] = h;
        lo[(size_t)r * C + c0 + tx] = l;
    }
    __syncthreads();
    #pragma unroll
    for (int i = 0; i < 4; i++) {
        const int c = c0 + ty + 8*i;
        float v = t[tx][ty + 8*i];
        __nv_bfloat16 h, l;
        split2(v, h, l);
        thi[(size_t)c * R + r0 + tx] = h;
        tlo[(size_t)c * R + r0 + tx] = l;
    }
}

// ------------------------- row softmax over LM, writes split-bf16 weights -------------------------
__global__ __launch_bounds__(256)
void softmax_split(const float* __restrict__ x, __nv_bfloat16* __restrict__ whi,
                   __nv_bfloat16* __restrict__ wlo)
{
    const float* row = x + (size_t)blockIdx.x * LM;
    __nv_bfloat16* rh = whi + (size_t)blockIdx.x * LM;
    __nv_bfloat16* rl = wlo + (size_t)blockIdx.x * LM;
    const int t = threadIdx.x;
    __shared__ float smax[8], ssum[8];

    float v[8];
    float m = -3.0e38f;
    #pragma unroll
    for (int i = 0; i < 8; i++) { v[i] = row[t + i*256]; m = fmaxf(m, v[i]); }
    #pragma unroll
    for (int o = 16; o > 0; o >>= 1) m = fmaxf(m, __shfl_xor_sync(0xFFFFFFFFu, m, o));
    if ((t & 31) == 0) smax[t >> 5] = m;
    __syncthreads();
    m = smax[0];
    #pragma unroll
    for (int i = 1; i < 8; i++) m = fmaxf(m, smax[i]);

    float s = 0.0f;
    #pragma unroll
    for (int i = 0; i < 8; i++) { v[i] = expf(v[i] - m); s += v[i]; }
    #pragma unroll
    for (int o = 16; o > 0; o >>= 1) s += __shfl_xor_sync(0xFFFFFFFFu, s, o);
    if ((t & 31) == 0) ssum[t >> 5] = s;
    __syncthreads();
    s = 0.0f;
    #pragma unroll
    for (int i = 0; i < 8; i++) s += ssum[i];
    const float inv = 1.0f / s;

    #pragma unroll
    for (int i = 0; i < 8; i++) {
        float w = v[i] * inv;
        __nv_bfloat16 h, l;
        split2(w, h, l);
        rh[t + i*256] = h;
        rl[t + i*256] = l;
    }
}

// ------------------------- launch -------------------------
extern "C" void kernel_launch(void* const* d_in, const int* in_sizes, int n_in,
                              void* d_out, int out_size)
{
    (void)in_sizes; (void)n_in; (void)out_size;
    const float* query    = (const float*)d_in[0];
    const float* memories = (const float*)d_in[1];
    const int*   mask     = (const int*)d_in[2];
    const float* W        = (const float*)d_in[3];
    const float* bvec     = (const float*)d_in[4];
    float*       out      = (float*)d_out;

    __nv_bfloat16 *qryhi, *qrylo, *Whi, *Wlo, *qhi, *qlo, *mhi, *mlo, *mThi, *mTlo, *whi, *wlo;
    float *logits;
    cudaGetSymbolAddress((void**)&qryhi, g_qryhi);  cudaGetSymbolAddress((void**)&qrylo, g_qrylo);
    cudaGetSymbolAddress((void**)&Whi,   g_Whi);    cudaGetSymbolAddress((void**)&Wlo,   g_Wlo);
    cudaGetSymbolAddress((void**)&qhi,   g_qhi);    cudaGetSymbolAddress((void**)&qlo,   g_qlo);
    cudaGetSymbolAddress((void**)&mhi,   g_mhi);    cudaGetSymbolAddress((void**)&mlo,   g_mlo);
    cudaGetSymbolAddress((void**)&mThi,  g_mThi);   cudaGetSymbolAddress((void**)&mTlo,  g_mTlo);
    cudaGetSymbolAddress((void**)&whi,   g_whi);    cudaGetSymbolAddress((void**)&wlo,   g_wlo);
    cudaGetSymbolAddress((void**)&logits, g_logits);

    const int SMEM = NSTAGE * STAGEB;   // 196608 B
    cudaFuncSetAttribute(gemm_mma<1>, cudaFuncAttributeMaxDynamicSharedMemorySize, SMEM);
    cudaFuncSetAttribute(gemm_mma<2>, cudaFuncAttributeMaxDynamicSharedMemorySize, SMEM);
    cudaFuncSetAttribute(gemm_mma<3>, cudaFuncAttributeMaxDynamicSharedMemorySize, SMEM);

    const size_t nQ = (size_t)BB * LQ * DD;
    const size_t nW = (size_t)DD * DD;

    // 0) split query + W; fused split+transpose for memories
    split_kernel<<<(unsigned)(nQ / 1024), 256>>>(query, qryhi, qrylo, nQ);
    split_kernel<<<(unsigned)(nW / 1024), 256>>>(W,     Whi,   Wlo,   nW);
    split_transpose_kernel<<<dim3(DD/32, LM/32, BB), dim3(32, 8)>>>(
        memories, mhi, mlo, mThi, mTlo, LM, DD);

    // 1) q = query @ W^T + b -> split bf16   (M=16384, N=1024, K=1024)
    gemm_mma<1><<<dim3(DD/256, (BB*LQ)/128, 1), 512, SMEM>>>(
        qryhi, qrylo, Whi, Wlo, bvec, nullptr, nullptr, qhi, qlo,
        DD, DD, (size_t)0, (size_t)0, (size_t)0);

    // 2) logits = q @ mem^T + mask  (per batch 2048x2048x1024) -> fp32
    gemm_mma<2><<<dim3(LM/256, LQ/128, BB), 512, SMEM>>>(
        qhi, qlo, mhi, mlo, nullptr, mask, logits, nullptr, nullptr,
        LM, DD, (size_t)LQ*DD, (size_t)LM*DD, (size_t)LQ*LM);

    // 3) softmax -> split bf16 weights
    softmax_split<<<BB*LQ, 256>>>(logits, whi, wlo);

    // 4) out = weights @ memT^T   (per batch 2048x1024x2048) -> fp32
    gemm_mma<3><<<dim3(DD/256, LQ/128, BB), 512, SMEM>>>(
        whi, wlo, mThi, mTlo, nullptr, nullptr, out, nullptr, nullptr,
        DD, LM, (size_t)LQ*LM, (size_t)DD*LM, (size_t)LQ*DD);
}

// round 9
// speedup vs baseline: 1.5326x; 1.5326x over previous
#include <cuda_runtime.h>
#include <cuda_bf16.h>
#include <cstdint>

#define BB 8
#define LQ 2048
#define LM 2048
#define DD 1024
#define NEGV (-1000000.0f)

// ------------------------- scratch (device globals) -------------------------
__device__ __nv_bfloat16 g_qryhi[(size_t)BB*LQ*DD], g_qrylo[(size_t)BB*LQ*DD];
__device__ __nv_bfloat16 g_Whi[(size_t)DD*DD],      g_Wlo[(size_t)DD*DD];
__device__ __nv_bfloat16 g_qhi[(size_t)BB*LQ*DD],   g_qlo[(size_t)BB*LQ*DD];
__device__ __nv_bfloat16 g_mhi[(size_t)BB*LM*DD],   g_mlo[(size_t)BB*LM*DD];
__device__ __nv_bfloat16 g_mThi[(size_t)BB*DD*LM],  g_mTlo[(size_t)BB*DD*LM];
__device__ float         g_logits[(size_t)BB*LQ*LM];
__device__ __nv_bfloat16 g_whi[(size_t)BB*LQ*LM],   g_wlo[(size_t)BB*LQ*LM];

// ------------------------- helpers -------------------------
__device__ __forceinline__ uint32_t smem_u32(const void* p) {
    uint32_t a;
    asm("{ .reg .u64 t; cvta.to.shared.u64 t, %1; cvt.u32.u64 %0, t; }" : "=r"(a) : "l"(p));
    return a;
}
__device__ __forceinline__ void cp16(uint32_t s, const void* g) {
    asm volatile("cp.async.cg.shared.global [%0], [%1], 16;" :: "r"(s), "l"(g));
}
__device__ __forceinline__ void ldmx4(uint32_t* r, uint32_t a) {
    asm volatile("ldmatrix.sync.aligned.m8n8.x4.shared.b16 {%0,%1,%2,%3}, [%4];"
                 : "=r"(r[0]), "=r"(r[1]), "=r"(r[2]), "=r"(r[3]) : "r"(a));
}
__device__ __forceinline__ void mma16816(float* c, const uint32_t* a, uint32_t b0, uint32_t b1) {
    asm volatile(
        "mma.sync.aligned.m16n8k16.row.col.f32.bf16.bf16.f32 "
        "{%0,%1,%2,%3}, {%4,%5,%6,%7}, {%8,%9}, {%0,%1,%2,%3};"
        : "+f"(c[0]), "+f"(c[1]), "+f"(c[2]), "+f"(c[3])
        : "r"(a[0]), "r"(a[1]), "r"(a[2]), "r"(a[3]), "r"(b0), "r"(b1));
}
__device__ __forceinline__ void split2(float v, __nv_bfloat16& h, __nv_bfloat16& l) {
    h = __float2bfloat16(v);
    l = __float2bfloat16(v - __bfloat162float(h));
}

// ------------------------- split-bf16 mma.sync GEMM (NT, K-major) -------------------------
// C[M,N] = (Ahi+Alo)[M,K]*(Bhi+Blo)[N,K]^T, 3 MMA terms, fp32 accum.
// CTA tile 128(M) x 256(N), 512 threads = 16 warps (2x8), warp tile 64x32.
// K-chunk 64 (one 128B SMEM row per M/N row per chunk), XOR-swizzled, 2 stages.
// Inner loop: term-major MMA order (16 independent MMAs between acc reuse).
// EPI: 1 = +bias -> split bf16 ; 2 = +mask NEG -> fp32 ; 3 = plain -> fp32.

#define ROWB 128
#define ATILEB (128 * ROWB)            // 16384
#define BTILEB (256 * ROWB)            // 32768
#define STAGEB (2*ATILEB + 2*BTILEB)   // 98304
#define NSTAGE 2

// Coalesced + swizzled loader: 8 lanes cover one 128B row; chunk' = chunk ^ (row&7).
__device__ __forceinline__ void load_tileA(uint32_t st, const __nv_bfloat16* g, int K, int k0, int tid) {
    #pragma unroll
    for (int p = 0; p < 2; p++) {
        int idx = p * 512 + tid;          // 0..1023
        int row = idx >> 3, c = idx & 7;
        cp16(st + (uint32_t)row * ROWB + (uint32_t)((c ^ (row & 7)) << 4),
             g + (size_t)row * K + k0 + c * 8);
    }
}
__device__ __forceinline__ void load_tileB(uint32_t st, const __nv_bfloat16* g, int K, int k0, int tid) {
    #pragma unroll
    for (int p = 0; p < 4; p++) {
        int idx = p * 512 + tid;          // 0..2047
        int row = idx >> 3, c = idx & 7;
        cp16(st + (uint32_t)row * ROWB + (uint32_t)((c ^ (row & 7)) << 4),
             g + (size_t)row * K + k0 + c * 8);
    }
}

template<int EPI>
__global__ __launch_bounds__(512)
void gemm_mma(const __nv_bfloat16* __restrict__ Ahi, const __nv_bfloat16* __restrict__ Alo,
              const __nv_bfloat16* __restrict__ Bhi, const __nv_bfloat16* __restrict__ Blo,
              const float* __restrict__ bias, const int* __restrict__ mask,
              float* __restrict__ Cf,
              __nv_bfloat16* __restrict__ Chi, __nv_bfloat16* __restrict__ Clo,
              int N, int K, size_t sA, size_t sB, size_t sC)
{
    extern __shared__ __align__(128) char dynsmem[];
    const int tid  = threadIdx.x;
    const int bz   = blockIdx.z;
    const int bm   = blockIdx.y * 128;
    const int bn   = blockIdx.x * 256;
    const int wid  = tid >> 5;
    const int lane = tid & 31;
    const int wm   = (wid >> 3) * 64;     // 0, 64
    const int wn   = (wid & 7) * 32;      // 0..224

    const uint32_t sb = smem_u32(dynsmem);

    const __nv_bfloat16* pAh = Ahi + (size_t)bz * sA + (size_t)bm * K;
    const __nv_bfloat16* pAl = Alo + (size_t)bz * sA + (size_t)bm * K;
    const __nv_bfloat16* pBh = Bhi + (size_t)bz * sB + (size_t)bn * K;
    const __nv_bfloat16* pBl = Blo + (size_t)bz * sB + (size_t)bn * K;

    float acc[4][4][4];
    #pragma unroll
    for (int i = 0; i < 4; i++)
        #pragma unroll
        for (int j = 0; j < 4; j++)
            #pragma unroll
            for (int r = 0; r < 4; r++) acc[i][j][r] = 0.0f;

    const int nk = K >> 6;   // 64-wide k-chunks

    // prologue: stage 0
    {
        load_tileA(sb,                     pAh, K, 0, tid);
        load_tileA(sb + ATILEB,            pAl, K, 0, tid);
        load_tileB(sb + 2*ATILEB,          pBh, K, 0, tid);
        load_tileB(sb + 2*ATILEB + BTILEB, pBl, K, 0, tid);
        asm volatile("cp.async.commit_group;" ::: "memory");
    }

    const uint32_t rowoff = (uint32_t)(lane & 15) * ROWB;
    const int      key    = lane & 7;
    const int      cbase  = lane >> 4;

    for (int c = 0; c < nk; ++c) {
        asm volatile("cp.async.wait_group 0;" ::: "memory");
        __syncthreads();

        if (c + 1 < nk) {
            uint32_t st = sb + (uint32_t)((c + 1) & 1) * STAGEB;
            int k0 = (c + 1) << 6;
            load_tileA(st,                     pAh, K, k0, tid);
            load_tileA(st + ATILEB,            pAl, K, k0, tid);
            load_tileB(st + 2*ATILEB,          pBh, K, k0, tid);
            load_tileB(st + 2*ATILEB + BTILEB, pBl, K, k0, tid);
            asm volatile("cp.async.commit_group;" ::: "memory");
        }

        const uint32_t st = sb + (uint32_t)(c & 1) * STAGEB;
        const uint32_t aH = st + (uint32_t)wm * ROWB + rowoff;
        const uint32_t aL = aH + ATILEB;
        const uint32_t bH = st + 2*ATILEB + (uint32_t)wn * ROWB + rowoff;
        const uint32_t bL = bH + BTILEB;

        #pragma unroll
        for (int kk = 0; kk < 4; kk++) {
            const uint32_t sw = (uint32_t)(((kk*2 + cbase) ^ key) << 4);
            uint32_t ah[4][4], al[4][4], bh[2][4], bl[2][4];
            #pragma unroll
            for (int h = 0; h < 2; h++) ldmx4(bh[h], bH + (uint32_t)h * (16 * ROWB) + sw);
            #pragma unroll
            for (int mt = 0; mt < 4; mt++) ldmx4(ah[mt], aH + (uint32_t)mt * (16 * ROWB) + sw);
            #pragma unroll
            for (int mt = 0; mt < 4; mt++) ldmx4(al[mt], aL + (uint32_t)mt * (16 * ROWB) + sw);
            #pragma unroll
            for (int h = 0; h < 2; h++) ldmx4(bl[h], bL + (uint32_t)h * (16 * ROWB) + sw);

            // term 1: ahi x bhi  (16 independent MMAs)
            #pragma unroll
            for (int mt = 0; mt < 4; mt++)
                #pragma unroll
                for (int nt = 0; nt < 4; nt++) {
                    const int g = nt >> 1, s = nt & 1;
                    mma16816(acc[mt][nt], ah[mt], bh[g][s], bh[g][s + 2]);
                }
            // term 2: alo x bhi
            #pragma unroll
            for (int mt = 0; mt < 4; mt++)
                #pragma unroll
                for (int nt = 0; nt < 4; nt++) {
                    const int g = nt >> 1, s = nt & 1;
                    mma16816(acc[mt][nt], al[mt], bh[g][s], bh[g][s + 2]);
                }
            // term 3: ahi x blo
            #pragma unroll
            for (int mt = 0; mt < 4; mt++)
                #pragma unroll
                for (int nt = 0; nt < 4; nt++) {
                    const int g = nt >> 1, s = nt & 1;
                    mma16816(acc[mt][nt], ah[mt], bl[g][s], bl[g][s + 2]);
                }
        }
    }

    // ---------------- epilogue ----------------
    const int r0 = lane >> 2;
    const int c0 = (lane & 3) * 2;

    #pragma unroll
    for (int mt = 0; mt < 4; mt++) {
        #pragma unroll
        for (int half = 0; half < 2; half++) {
            const size_t grow = (size_t)(bm + wm + mt * 16 + r0 + half * 8);
            #pragma unroll
            for (int nt = 0; nt < 4; nt++) {
                const int gcol = bn + wn + nt * 8 + c0;
                float v0 = acc[mt][nt][half * 2 + 0];
                float v1 = acc[mt][nt][half * 2 + 1];

                if (EPI == 1) {
                    v0 += bias[gcol];
                    v1 += bias[gcol + 1];
                    __nv_bfloat16 h0, l0, h1, l1;
                    split2(v0, h0, l0); split2(v1, h1, l1);
                    uint32_t ph = ((uint32_t)__bfloat16_as_ushort(h1) << 16) | __bfloat16_as_ushort(h0);
                    uint32_t pl = ((uint32_t)__bfloat16_as_ushort(l1) << 16) | __bfloat16_as_ushort(l0);
                    *(uint32_t*)(Chi + (size_t)bz * sC + grow * N + gcol) = ph;
                    *(uint32_t*)(Clo + (size_t)bz * sC + grow * N + gcol) = pl;
                } else if (EPI == 2) {
                    int2 mm = *(const int2*)(mask + (size_t)bz * sC + grow * N + gcol);
                    float2 vv;
                    vv.x = v0 + (mm.x ? 0.0f : NEGV);
                    vv.y = v1 + (mm.y ? 0.0f : NEGV);
                    *(float2*)(Cf + (size_t)bz * sC + grow * N + gcol) = vv;
                } else {
                    *(float2*)(Cf + (size_t)bz * sC + grow * N + gcol) = make_float2(v0, v1);
                }
            }
        }
    }
}

// ------------------------- elementwise split fp32 -> (hi,lo) bf16 -------------------------
__global__ __launch_bounds__(256)
void split_kernel(const float* __restrict__ x, __nv_bfloat16* __restrict__ hi,
                  __nv_bfloat16* __restrict__ lo, size_t n)
{
    size_t i = ((size_t)blockIdx.x * 256 + threadIdx.x) * 4;
    if (i >= n) return;
    float4 v = *(const float4*)(x + i);
    float f[4] = {v.x, v.y, v.z, v.w};
    uint32_t ph[2], pl[2];
    #pragma unroll
    for (int j = 0; j < 2; j++) {
        __nv_bfloat16 h0, l0, h1, l1;
        split2(f[2*j], h0, l0); split2(f[2*j+1], h1, l1);
        ph[j] = ((uint32_t)__bfloat16_as_ushort(h1) << 16) | __bfloat16_as_ushort(h0);
        pl[j] = ((uint32_t)__bfloat16_as_ushort(l1) << 16) | __bfloat16_as_ushort(l0);
    }
    *(uint2*)(hi + i) = make_uint2(ph[0], ph[1]);
    *(uint2*)(lo + i) = make_uint2(pl[0], pl[1]);
}

// ---------------- fused: memories fp32 -> split row-major AND split transposed ----------------
__global__ __launch_bounds__(256)
void split_transpose_kernel(const float* __restrict__ src,
                            __nv_bfloat16* __restrict__ hi, __nv_bfloat16* __restrict__ lo,
                            __nv_bfloat16* __restrict__ thi, __nv_bfloat16* __restrict__ tlo,
                            int R, int C)
{
    __shared__ float t[32][33];
    const int z = blockIdx.z;
    src += (size_t)z * R * C;
    hi  += (size_t)z * R * C;  lo  += (size_t)z * R * C;
    thi += (size_t)z * R * C;  tlo += (size_t)z * R * C;
    const int c0 = blockIdx.x * 32, r0 = blockIdx.y * 32;
    const int tx = threadIdx.x, ty = threadIdx.y;

    #pragma unroll
    for (int i = 0; i < 4; i++) {
        const int r = r0 + ty + 8*i;
        float v = src[(size_t)r * C + c0 + tx];
        t[ty + 8*i][tx] = v;
        __nv_bfloat16 h, l;
        split2(v, h, l);
        hi[(size_t)r * C + c0 + tx] = h;
        lo[(size_t)r * C + c0 + tx] = l;
    }
    __syncthreads();
    #pragma unroll
    for (int i = 0; i < 4; i++) {
        const int c = c0 + ty + 8*i;
        float v = t[tx][ty + 8*i];
        __nv_bfloat16 h, l;
        split2(v, h, l);
        thi[(size_t)c * R + r0 + tx] = h;
        tlo[(size_t)c * R + r0 + tx] = l;
    }
}

// ------------------------- row softmax over LM, writes split-bf16 weights -------------------------
__global__ __launch_bounds__(256)
void softmax_split(const float* __restrict__ x, __nv_bfloat16* __restrict__ whi,
                   __nv_bfloat16* __restrict__ wlo)
{
    const float* row = x + (size_t)blockIdx.x * LM;
    __nv_bfloat16* rh = whi + (size_t)blockIdx.x * LM;
    __nv_bfloat16* rl = wlo + (size_t)blockIdx.x * LM;
    const int t = threadIdx.x;
    __shared__ float smax[8], ssum[8];

    float v[8];
    float m = -3.0e38f;
    #pragma unroll
    for (int i = 0; i < 8; i++) { v[i] = row[t + i*256]; m = fmaxf(m, v[i]); }
    #pragma unroll
    for (int o = 16; o > 0; o >>= 1) m = fmaxf(m, __shfl_xor_sync(0xFFFFFFFFu, m, o));
    if ((t & 31) == 0) smax[t >> 5] = m;
    __syncthreads();
    m = smax[0];
    #pragma unroll
    for (int i = 1; i < 8; i++) m = fmaxf(m, smax[i]);

    float s = 0.0f;
    #pragma unroll
    for (int i = 0; i < 8; i++) { v[i] = expf(v[i] - m); s += v[i]; }
    #pragma unroll
    for (int o = 16; o > 0; o >>= 1) s += __shfl_xor_sync(0xFFFFFFFFu, s, o);
    if ((t & 31) == 0) ssum[t >> 5] = s;
    __syncthreads();
    s = 0.0f;
    #pragma unroll
    for (int i = 0; i < 8; i++) s += ssum[i];
    const float inv = 1.0f / s;

    #pragma unroll
    for (int i = 0; i < 8; i++) {
        float w = v[i] * inv;
        __nv_bfloat16 h, l;
        split2(w, h, l);
        rh[t + i*256] = h;
        rl[t + i*256] = l;
    }
}

// ------------------------- launch -------------------------
extern "C" void kernel_launch(void* const* d_in, const int* in_sizes, int n_in,
                              void* d_out, int out_size)
{
    (void)in_sizes; (void)n_in; (void)out_size;
    const float* query    = (const float*)d_in[0];
    const float* memories = (const float*)d_in[1];
    const int*   mask     = (const int*)d_in[2];
    const float* W        = (const float*)d_in[3];
    const float* bvec     = (const float*)d_in[4];
    float*       out      = (float*)d_out;

    __nv_bfloat16 *qryhi, *qrylo, *Whi, *Wlo, *qhi, *qlo, *mhi, *mlo, *mThi, *mTlo, *whi, *wlo;
    float *logits;
    cudaGetSymbolAddress((void**)&qryhi, g_qryhi);  cudaGetSymbolAddress((void**)&qrylo, g_qrylo);
    cudaGetSymbolAddress((void**)&Whi,   g_Whi);    cudaGetSymbolAddress((void**)&Wlo,   g_Wlo);
    cudaGetSymbolAddress((void**)&qhi,   g_qhi);    cudaGetSymbolAddress((void**)&qlo,   g_qlo);
    cudaGetSymbolAddress((void**)&mhi,   g_mhi);    cudaGetSymbolAddress((void**)&mlo,   g_mlo);
    cudaGetSymbolAddress((void**)&mThi,  g_mThi);   cudaGetSymbolAddress((void**)&mTlo,  g_mTlo);
    cudaGetSymbolAddress((void**)&whi,   g_whi);    cudaGetSymbolAddress((void**)&wlo,   g_wlo);
    cudaGetSymbolAddress((void**)&logits, g_logits);

    const int SMEM = NSTAGE * STAGEB;   // 196608 B
    cudaFuncSetAttribute(gemm_mma<1>, cudaFuncAttributeMaxDynamicSharedMemorySize, SMEM);
    cudaFuncSetAttribute(gemm_mma<2>, cudaFuncAttributeMaxDynamicSharedMemorySize, SMEM);
    cudaFuncSetAttribute(gemm_mma<3>, cudaFuncAttributeMaxDynamicSharedMemorySize, SMEM);

    const size_t nQ = (size_t)BB * LQ * DD;
    const size_t nW = (size_t)DD * DD;

    // 0) split query + W; fused split+transpose for memories
    split_kernel<<<(unsigned)(nQ / 1024), 256>>>(query, qryhi, qrylo, nQ);
    split_kernel<<<(unsigned)(nW / 1024), 256>>>(W,     Whi,   Wlo,   nW);
    split_transpose_kernel<<<dim3(DD/32, LM/32, BB), dim3(32, 8)>>>(
        memories, mhi, mlo, mThi, mTlo, LM, DD);

    // 1) q = query @ W^T + b -> split bf16   (M=16384, N=1024, K=1024)
    gemm_mma<1><<<dim3(DD/256, (BB*LQ)/128, 1), 512, SMEM>>>(
        qryhi, qrylo, Whi, Wlo, bvec, nullptr, nullptr, qhi, qlo,
        DD, DD, (size_t)0, (size_t)0, (size_t)0);

    // 2) logits = q @ mem^T + mask  (per batch 2048x2048x1024) -> fp32
    gemm_mma<2><<<dim3(LM/256, LQ/128, BB), 512, SMEM>>>(
        qhi, qlo, mhi, mlo, nullptr, mask, logits, nullptr, nullptr,
        LM, DD, (size_t)LQ*DD, (size_t)LM*DD, (size_t)LQ*LM);

    // 3) softmax -> split bf16 weights
    softmax_split<<<BB*LQ, 256>>>(logits, whi, wlo);

    // 4) out = weights @ memT^T   (per batch 2048x1024x2048) -> fp32
    gemm_mma<3><<<dim3(DD/256, LQ/128, BB), 512, SMEM>>>(
        whi, wlo, mThi, mTlo, nullptr, nullptr, out, nullptr, nullptr,
        DD, LM, (size_t)LQ*LM, (size_t)DD*LM, (size_t)LQ*DD);
}

// round 10
// speedup vs baseline: 1.5392x; 1.0043x over previous
#include <cuda_runtime.h>
#include <cuda_bf16.h>
#include <cstdint>

#define BB 8
#define LQ 2048
#define LM 2048
#define DD 1024
#define NEGV (-1000000.0f)

// ------------------------- scratch (device globals) -------------------------
__device__ __nv_bfloat16 g_qryhi[(size_t)BB*LQ*DD], g_qrylo[(size_t)BB*LQ*DD];
__device__ __nv_bfloat16 g_Whi[(size_t)DD*DD],      g_Wlo[(size_t)DD*DD];
__device__ __nv_bfloat16 g_qhi[(size_t)BB*LQ*DD],   g_qlo[(size_t)BB*LQ*DD];
__device__ __nv_bfloat16 g_mhi[(size_t)BB*LM*DD],   g_mlo[(size_t)BB*LM*DD];
__device__ __nv_bfloat16 g_mThi[(size_t)BB*DD*LM],  g_mTlo[(size_t)BB*DD*LM];
__device__ float         g_logits[(size_t)BB*LQ*LM];
__device__ __nv_bfloat16 g_whi[(size_t)BB*LQ*LM],   g_wlo[(size_t)BB*LQ*LM];

// ------------------------- helpers -------------------------
__device__ __forceinline__ uint32_t smem_u32(const void* p) {
    uint32_t a;
    asm("{ .reg .u64 t; cvta.to.shared.u64 t, %1; cvt.u32.u64 %0, t; }" : "=r"(a) : "l"(p));
    return a;
}
__device__ __forceinline__ void cp16(uint32_t s, const void* g) {
    asm volatile("cp.async.cg.shared.global [%0], [%1], 16;" :: "r"(s), "l"(g));
}
__device__ __forceinline__ void ldmx4(uint32_t* r, uint32_t a) {
    asm volatile("ldmatrix.sync.aligned.m8n8.x4.shared.b16 {%0,%1,%2,%3}, [%4];"
                 : "=r"(r[0]), "=r"(r[1]), "=r"(r[2]), "=r"(r[3]) : "r"(a));
}
__device__ __forceinline__ void mma16816(float* c, const uint32_t* a, uint32_t b0, uint32_t b1) {
    asm volatile(
        "mma.sync.aligned.m16n8k16.row.col.f32.bf16.bf16.f32 "
        "{%0,%1,%2,%3}, {%4,%5,%6,%7}, {%8,%9}, {%0,%1,%2,%3};"
        : "+f"(c[0]), "+f"(c[1]), "+f"(c[2]), "+f"(c[3])
        : "r"(a[0]), "r"(a[1]), "r"(a[2]), "r"(a[3]), "r"(b0), "r"(b1));
}
__device__ __forceinline__ void split2(float v, __nv_bfloat16& h, __nv_bfloat16& l) {
    h = __float2bfloat16(v);
    l = __float2bfloat16(v - __bfloat162float(h));
}

// ------------------------- split-bf16 mma.sync GEMM (NT, K-major) -------------------------
// C[M,N] = (Ahi+Alo)[M,K]*(Bhi+Blo)[N,K]^T, 3 MMA terms, fp32 accum.
// CTA tile 128(M) x 256(N), 256 threads = 8 warps (2x4), warp tile 64x64.
// K-chunk 64 (one 128B SMEM row per M/N row), XOR-swizzled, 2 stages.
// Term-major MMA issue (32 independent MMAs between accumulator reuse).
// EPI: 1 = +bias -> split bf16 ; 2 = +mask NEG -> fp32 ; 3 = plain -> fp32.

#define ROWB 128
#define ATILEB (128 * ROWB)            // 16384
#define BTILEB (256 * ROWB)            // 32768
#define STAGEB (2*ATILEB + 2*BTILEB)   // 98304
#define NSTAGE 2

// Coalesced + swizzled loaders (256 threads): 8 lanes cover one 128B row.
__device__ __forceinline__ void load_tileA(uint32_t st, const __nv_bfloat16* g, int K, int k0, int tid) {
    #pragma unroll
    for (int p = 0; p < 4; p++) {
        int idx = p * 256 + tid;          // 0..1023
        int row = idx >> 3, c = idx & 7;
        cp16(st + (uint32_t)row * ROWB + (uint32_t)((c ^ (row & 7)) << 4),
             g + (size_t)row * K + k0 + c * 8);
    }
}
__device__ __forceinline__ void load_tileB(uint32_t st, const __nv_bfloat16* g, int K, int k0, int tid) {
    #pragma unroll
    for (int p = 0; p < 8; p++) {
        int idx = p * 256 + tid;          // 0..2047
        int row = idx >> 3, c = idx & 7;
        cp16(st + (uint32_t)row * ROWB + (uint32_t)((c ^ (row & 7)) << 4),
             g + (size_t)row * K + k0 + c * 8);
    }
}

template<int EPI>
__global__ __launch_bounds__(256)
void gemm_mma(const __nv_bfloat16* __restrict__ Ahi, const __nv_bfloat16* __restrict__ Alo,
              const __nv_bfloat16* __restrict__ Bhi, const __nv_bfloat16* __restrict__ Blo,
              const float* __restrict__ bias, const int* __restrict__ mask,
              float* __restrict__ Cf,
              __nv_bfloat16* __restrict__ Chi, __nv_bfloat16* __restrict__ Clo,
              int N, int K, size_t sA, size_t sB, size_t sC)
{
    extern __shared__ __align__(128) char dynsmem[];
    const int tid  = threadIdx.x;
    const int bz   = blockIdx.z;
    const int bm   = blockIdx.y * 128;
    const int bn   = blockIdx.x * 256;
    const int wid  = tid >> 5;
    const int lane = tid & 31;
    const int wm   = (wid >> 2) * 64;     // 0, 64
    const int wn   = (wid & 3) * 64;      // 0, 64, 128, 192

    const uint32_t sb = smem_u32(dynsmem);

    const __nv_bfloat16* pAh = Ahi + (size_t)bz * sA + (size_t)bm * K;
    const __nv_bfloat16* pAl = Alo + (size_t)bz * sA + (size_t)bm * K;
    const __nv_bfloat16* pBh = Bhi + (size_t)bz * sB + (size_t)bn * K;
    const __nv_bfloat16* pBl = Blo + (size_t)bz * sB + (size_t)bn * K;

    float acc[4][8][4];
    #pragma unroll
    for (int i = 0; i < 4; i++)
        #pragma unroll
        for (int j = 0; j < 8; j++)
            #pragma unroll
            for (int r = 0; r < 4; r++) acc[i][j][r] = 0.0f;

    const int nk = K >> 6;   // 64-wide k-chunks

    // prologue: stage 0
    {
        load_tileA(sb,                     pAh, K, 0, tid);
        load_tileA(sb + ATILEB,            pAl, K, 0, tid);
        load_tileB(sb + 2*ATILEB,          pBh, K, 0, tid);
        load_tileB(sb + 2*ATILEB + BTILEB, pBl, K, 0, tid);
        asm volatile("cp.async.commit_group;" ::: "memory");
    }

    const uint32_t rowoff = (uint32_t)(lane & 15) * ROWB;
    const int      key    = lane & 7;
    const int      cbase  = lane >> 4;

    for (int c = 0; c < nk; ++c) {
        asm volatile("cp.async.wait_group 0;" ::: "memory");
        __syncthreads();

        if (c + 1 < nk) {
            uint32_t st = sb + (uint32_t)((c + 1) & 1) * STAGEB;
            int k0 = (c + 1) << 6;
            load_tileA(st,                     pAh, K, k0, tid);
            load_tileA(st + ATILEB,            pAl, K, k0, tid);
            load_tileB(st + 2*ATILEB,          pBh, K, k0, tid);
            load_tileB(st + 2*ATILEB + BTILEB, pBl, K, k0, tid);
            asm volatile("cp.async.commit_group;" ::: "memory");
        }

        const uint32_t st = sb + (uint32_t)(c & 1) * STAGEB;
        const uint32_t aH = st + (uint32_t)wm * ROWB + rowoff;
        const uint32_t aL = aH + ATILEB;
        const uint32_t bH = st + 2*ATILEB + (uint32_t)wn * ROWB + rowoff;
        const uint32_t bL = bH + BTILEB;

        #pragma unroll
        for (int kk = 0; kk < 4; kk++) {
            const uint32_t sw = (uint32_t)(((kk*2 + cbase) ^ key) << 4);
            uint32_t ah[4][4], al[4][4], bh[4][4], bl[4][4];
            #pragma unroll
            for (int h = 0; h < 4; h++) ldmx4(bh[h], bH + (uint32_t)h * (16 * ROWB) + sw);
            #pragma unroll
            for (int mt = 0; mt < 4; mt++) ldmx4(ah[mt], aH + (uint32_t)mt * (16 * ROWB) + sw);
            #pragma unroll
            for (int mt = 0; mt < 4; mt++) ldmx4(al[mt], aL + (uint32_t)mt * (16 * ROWB) + sw);
            #pragma unroll
            for (int h = 0; h < 4; h++) ldmx4(bl[h], bL + (uint32_t)h * (16 * ROWB) + sw);

            // term 1: ahi x bhi  (32 independent MMAs)
            #pragma unroll
            for (int mt = 0; mt < 4; mt++)
                #pragma unroll
                for (int nt = 0; nt < 8; nt++) {
                    const int g = nt >> 1, s = nt & 1;
                    mma16816(acc[mt][nt], ah[mt], bh[g][s], bh[g][s + 2]);
                }
            // term 2: alo x bhi
            #pragma unroll
            for (int mt = 0; mt < 4; mt++)
                #pragma unroll
                for (int nt = 0; nt < 8; nt++) {
                    const int g = nt >> 1, s = nt & 1;
                    mma16816(acc[mt][nt], al[mt], bh[g][s], bh[g][s + 2]);
                }
            // term 3: ahi x blo
            #pragma unroll
            for (int mt = 0; mt < 4; mt++)
                #pragma unroll
                for (int nt = 0; nt < 8; nt++) {
                    const int g = nt >> 1, s = nt & 1;
                    mma16816(acc[mt][nt], ah[mt], bl[g][s], bl[g][s + 2]);
                }
        }
    }

    // ---------------- epilogue ----------------
    const int r0 = lane >> 2;
    const int c0 = (lane & 3) * 2;

    #pragma unroll
    for (int mt = 0; mt < 4; mt++) {
        #pragma unroll
        for (int half = 0; half < 2; half++) {
            const size_t grow = (size_t)(bm + wm + mt * 16 + r0 + half * 8);
            #pragma unroll
            for (int nt = 0; nt < 8; nt++) {
                const int gcol = bn + wn + nt * 8 + c0;
                float v0 = acc[mt][nt][half * 2 + 0];
                float v1 = acc[mt][nt][half * 2 + 1];

                if (EPI == 1) {
                    v0 += bias[gcol];
                    v1 += bias[gcol + 1];
                    __nv_bfloat16 h0, l0, h1, l1;
                    split2(v0, h0, l0); split2(v1, h1, l1);
                    uint32_t ph = ((uint32_t)__bfloat16_as_ushort(h1) << 16) | __bfloat16_as_ushort(h0);
                    uint32_t pl = ((uint32_t)__bfloat16_as_ushort(l1) << 16) | __bfloat16_as_ushort(l0);
                    *(uint32_t*)(Chi + (size_t)bz * sC + grow * N + gcol) = ph;
                    *(uint32_t*)(Clo + (size_t)bz * sC + grow * N + gcol) = pl;
                } else if (EPI == 2) {
                    int2 mm = *(const int2*)(mask + (size_t)bz * sC + grow * N + gcol);
                    float2 vv;
                    vv.x = v0 + (mm.x ? 0.0f : NEGV);
                    vv.y = v1 + (mm.y ? 0.0f : NEGV);
                    *(float2*)(Cf + (size_t)bz * sC + grow * N + gcol) = vv;
                } else {
                    *(float2*)(Cf + (size_t)bz * sC + grow * N + gcol) = make_float2(v0, v1);
                }
            }
        }
    }
}

// ------------------------- elementwise split fp32 -> (hi,lo) bf16 -------------------------
__global__ __launch_bounds__(256)
void split_kernel(const float* __restrict__ x, __nv_bfloat16* __restrict__ hi,
                  __nv_bfloat16* __restrict__ lo, size_t n)
{
    size_t i = ((size_t)blockIdx.x * 256 + threadIdx.x) * 4;
    if (i >= n) return;
    float4 v = *(const float4*)(x + i);
    float f[4] = {v.x, v.y, v.z, v.w};
    uint32_t ph[2], pl[2];
    #pragma unroll
    for (int j = 0; j < 2; j++) {
        __nv_bfloat16 h0, l0, h1, l1;
        split2(f[2*j], h0, l0); split2(f[2*j+1], h1, l1);
        ph[j] = ((uint32_t)__bfloat16_as_ushort(h1) << 16) | __bfloat16_as_ushort(h0);
        pl[j] = ((uint32_t)__bfloat16_as_ushort(l1) << 16) | __bfloat16_as_ushort(l0);
    }
    *(uint2*)(hi + i) = make_uint2(ph[0], ph[1]);
    *(uint2*)(lo + i) = make_uint2(pl[0], pl[1]);
}

// ---------------- fused: memories fp32 -> split row-major AND split transposed ----------------
__global__ __launch_bounds__(256)
void split_transpose_kernel(const float* __restrict__ src,
                            __nv_bfloat16* __restrict__ hi, __nv_bfloat16* __restrict__ lo,
                            __nv_bfloat16* __restrict__ thi, __nv_bfloat16* __restrict__ tlo,
                            int R, int C)
{
    __shared__ float t[32][33];
    const int z = blockIdx.z;
    src += (size_t)z * R * C;
    hi  += (size_t)z * R * C;  lo  += (size_t)z * R * C;
    thi += (size_t)z * R * C;  tlo += (size_t)z * R * C;
    const int c0 = blockIdx.x * 32, r0 = blockIdx.y * 32;
    const int tx = threadIdx.x, ty = threadIdx.y;

    #pragma unroll
    for (int i = 0; i < 4; i++) {
        const int r = r0 + ty + 8*i;
        float v = src[(size_t)r * C + c0 + tx];
        t[ty + 8*i][tx] = v;
        __nv_bfloat16 h, l;
        split2(v, h, l);
        hi[(size_t)r * C + c0 + tx] = h;
        lo[(size_t)r * C + c0 + tx] = l;
    }
    __syncthreads();
    #pragma unroll
    for (int i = 0; i < 4; i++) {
        const int c = c0 + ty + 8*i;
        float v = t[tx][ty + 8*i];
        __nv_bfloat16 h, l;
        split2(v, h, l);
        thi[(size_t)c * R + r0 + tx] = h;
        tlo[(size_t)c * R + r0 + tx] = l;
    }
}

// ------------------------- row softmax over LM, writes split-bf16 weights -------------------------
__global__ __launch_bounds__(256)
void softmax_split(const float* __restrict__ x, __nv_bfloat16* __restrict__ whi,
                   __nv_bfloat16* __restrict__ wlo)
{
    const float* row = x + (size_t)blockIdx.x * LM;
    __nv_bfloat16* rh = whi + (size_t)blockIdx.x * LM;
    __nv_bfloat16* rl = wlo + (size_t)blockIdx.x * LM;
    const int t = threadIdx.x;
    __shared__ float smax[8], ssum[8];

    float v[8];
    float m = -3.0e38f;
    #pragma unroll
    for (int i = 0; i < 8; i++) { v[i] = row[t + i*256]; m = fmaxf(m, v[i]); }
    #pragma unroll
    for (int o = 16; o > 0; o >>= 1) m = fmaxf(m, __shfl_xor_sync(0xFFFFFFFFu, m, o));
    if ((t & 31) == 0) smax[t >> 5] = m;
    __syncthreads();
    m = smax[0];
    #pragma unroll
    for (int i = 1; i < 8; i++) m = fmaxf(m, smax[i]);

    float s = 0.0f;
    #pragma unroll
    for (int i = 0; i < 8; i++) { v[i] = expf(v[i] - m); s += v[i]; }
    #pragma unroll
    for (int o = 16; o > 0; o >>= 1) s += __shfl_xor_sync(0xFFFFFFFFu, s, o);
    if ((t & 31) == 0) ssum[t >> 5] = s;
    __syncthreads();
    s = 0.0f;
    #pragma unroll
    for (int i = 0; i < 8; i++) s += ssum[i];
    const float inv = 1.0f / s;

    #pragma unroll
    for (int i = 0; i < 8; i++) {
        float w = v[i] * inv;
        __nv_bfloat16 h, l;
        split2(w, h, l);
        rh[t + i*256] = h;
        rl[t + i*256] = l;
    }
}

// ------------------------- launch -------------------------
extern "C" void kernel_launch(void* const* d_in, const int* in_sizes, int n_in,
                              void* d_out, int out_size)
{
    (void)in_sizes; (void)n_in; (void)out_size;
    const float* query    = (const float*)d_in[0];
    const float* memories = (const float*)d_in[1];
    const int*   mask     = (const int*)d_in[2];
    const float* W        = (const float*)d_in[3];
    const float* bvec     = (const float*)d_in[4];
    float*       out      = (float*)d_out;

    __nv_bfloat16 *qryhi, *qrylo, *Whi, *Wlo, *qhi, *qlo, *mhi, *mlo, *mThi, *mTlo, *whi, *wlo;
    float *logits;
    cudaGetSymbolAddress((void**)&qryhi, g_qryhi);  cudaGetSymbolAddress((void**)&qrylo, g_qrylo);
    cudaGetSymbolAddress((void**)&Whi,   g_Whi);    cudaGetSymbolAddress((void**)&Wlo,   g_Wlo);
    cudaGetSymbolAddress((void**)&qhi,   g_qhi);    cudaGetSymbolAddress((void**)&qlo,   g_qlo);
    cudaGetSymbolAddress((void**)&mhi,   g_mhi);    cudaGetSymbolAddress((void**)&mlo,   g_mlo);
    cudaGetSymbolAddress((void**)&mThi,  g_mThi);   cudaGetSymbolAddress((void**)&mTlo,  g_mTlo);
    cudaGetSymbolAddress((void**)&whi,   g_whi);    cudaGetSymbolAddress((void**)&wlo,   g_wlo);
    cudaGetSymbolAddress((void**)&logits, g_logits);

    const int SMEM = NSTAGE * STAGEB;   // 196608 B
    cudaFuncSetAttribute(gemm_mma<1>, cudaFuncAttributeMaxDynamicSharedMemorySize, SMEM);
    cudaFuncSetAttribute(gemm_mma<2>, cudaFuncAttributeMaxDynamicSharedMemorySize, SMEM);
    cudaFuncSetAttribute(gemm_mma<3>, cudaFuncAttributeMaxDynamicSharedMemorySize, SMEM);

    const size_t nQ = (size_t)BB * LQ * DD;
    const size_t nW = (size_t)DD * DD;

    // 0) split query + W; fused split+transpose for memories
    split_kernel<<<(unsigned)(nQ / 1024), 256>>>(query, qryhi, qrylo, nQ);
    split_kernel<<<(unsigned)(nW / 1024), 256>>>(W,     Whi,   Wlo,   nW);
    split_transpose_kernel<<<dim3(DD/32, LM/32, BB), dim3(32, 8)>>>(
        memories, mhi, mlo, mThi, mTlo, LM, DD);

    // 1) q = query @ W^T + b -> split bf16   (M=16384, N=1024, K=1024)
    gemm_mma<1><<<dim3(DD/256, (BB*LQ)/128, 1), 256, SMEM>>>(
        qryhi, qrylo, Whi, Wlo, bvec, nullptr, nullptr, qhi, qlo,
        DD, DD, (size_t)0, (size_t)0, (size_t)0);

    // 2) logits = q @ mem^T + mask  (per batch 2048x2048x1024) -> fp32
    gemm_mma<2><<<dim3(LM/256, LQ/128, BB), 256, SMEM>>>(
        qhi, qlo, mhi, mlo, nullptr, mask, logits, nullptr, nullptr,
        LM, DD, (size_t)LQ*DD, (size_t)LM*DD, (size_t)LQ*LM);

    // 3) softmax -> split bf16 weights
    softmax_split<<<BB*LQ, 256>>>(logits, whi, wlo);

    // 4) out = weights @ memT^T   (per batch 2048x1024x2048) -> fp32
    gemm_mma<3><<<dim3(DD/256, LQ/128, BB), 256, SMEM>>>(
        whi, wlo, mThi, mTlo, nullptr, nullptr, out, nullptr, nullptr,
        DD, LM, (size_t)LQ*LM, (size_t)DD*LM, (size_t)LQ*DD);
}

// round 11
// speedup vs baseline: 2.0330x; 1.3208x over previous
#include <cuda_runtime.h>
#include <cuda_fp16.h>
#include <cstdint>

#define BB 8
#define LQ 2048
#define LM 2048
#define DD 1024
#define NEGV (-1000000.0f)

// ------------------------- scratch (device globals) -------------------------
__device__ __half g_qryh[(size_t)BB*LQ*DD], g_qryl[(size_t)BB*LQ*DD];
__device__ __half g_Wh[(size_t)DD*DD],      g_Wl[(size_t)DD*DD];
__device__ __half g_qh[(size_t)BB*LQ*DD],   g_ql[(size_t)BB*LQ*DD];
__device__ __half g_mh[(size_t)BB*LM*DD];                     // memories, single fp16, K-major
__device__ __half g_mTh[(size_t)BB*DD*LM],  g_mTl[(size_t)BB*DD*LM]; // transposed split
__device__ float  g_logits[(size_t)BB*LQ*LM];
__device__ __half g_w[(size_t)BB*LQ*LM];                      // softmax weights, single fp16

// ------------------------- helpers -------------------------
__device__ __forceinline__ uint32_t smem_u32(const void* p) {
    uint32_t a;
    asm("{ .reg .u64 t; cvta.to.shared.u64 t, %1; cvt.u32.u64 %0, t; }" : "=r"(a) : "l"(p));
    return a;
}
__device__ __forceinline__ void cp16(uint32_t s, const void* g) {
    asm volatile("cp.async.cg.shared.global [%0], [%1], 16;" :: "r"(s), "l"(g));
}
__device__ __forceinline__ void ldmx4(uint32_t* r, uint32_t a) {
    asm volatile("ldmatrix.sync.aligned.m8n8.x4.shared.b16 {%0,%1,%2,%3}, [%4];"
                 : "=r"(r[0]), "=r"(r[1]), "=r"(r[2]), "=r"(r[3]) : "r"(a));
}
__device__ __forceinline__ void mma16816(float* c, const uint32_t* a, uint32_t b0, uint32_t b1) {
    asm volatile(
        "mma.sync.aligned.m16n8k16.row.col.f32.f16.f16.f32 "
        "{%0,%1,%2,%3}, {%4,%5,%6,%7}, {%8,%9}, {%0,%1,%2,%3};"
        : "+f"(c[0]), "+f"(c[1]), "+f"(c[2]), "+f"(c[3])
        : "r"(a[0]), "r"(a[1]), "r"(a[2]), "r"(a[3]), "r"(b0), "r"(b1));
}
__device__ __forceinline__ void split2h(float v, __half& h, __half& l) {
    h = __float2half_rn(v);
    l = __float2half_rn(v - __half2float(h));
}

// ------------------------- fp16 split mma.sync GEMM (NT, K-major) -------------------------
// CTA tile 128(M) x 256(N), 256 threads = 8 warps (2x4), warp tile 64x64.
// K-chunk 64, XOR-swizzled 128B SMEM rows, 2 stages, term-major MMA order.
// MODE 1: C=(A1+A2)(B1+B2)^T 3-term, +bias, out split-fp16 (Ch,Cl)
// MODE 2: C=(A1+A2)·B1^T     2-term, +mask NEG, out fp32
// MODE 3: C=A1·(B1+B2)^T     2-term, plain, out fp32

#define ROWB 128
#define ATILEB (128 * ROWB)            // 16384
#define BTILEB (256 * ROWB)            // 32768
#define STAGEB (2*ATILEB + 2*BTILEB)   // 98304 (max across modes; fixed offsets)
#define NSTAGE 2

__device__ __forceinline__ void load_tileA(uint32_t st, const __half* g, int K, int k0, int tid) {
    #pragma unroll
    for (int p = 0; p < 4; p++) {
        int idx = p * 256 + tid;
        int row = idx >> 3, c = idx & 7;
        cp16(st + (uint32_t)row * ROWB + (uint32_t)((c ^ (row & 7)) << 4),
             g + (size_t)row * K + k0 + c * 8);
    }
}
__device__ __forceinline__ void load_tileB(uint32_t st, const __half* g, int K, int k0, int tid) {
    #pragma unroll
    for (int p = 0; p < 8; p++) {
        int idx = p * 256 + tid;
        int row = idx >> 3, c = idx & 7;
        cp16(st + (uint32_t)row * ROWB + (uint32_t)((c ^ (row & 7)) << 4),
             g + (size_t)row * K + k0 + c * 8);
    }
}

template<int MODE>
__global__ __launch_bounds__(256)
void gemm_mma(const __half* __restrict__ A1, const __half* __restrict__ A2,
              const __half* __restrict__ B1, const __half* __restrict__ B2,
              const float* __restrict__ bias, const int* __restrict__ mask,
              float* __restrict__ Cf, __half* __restrict__ Ch, __half* __restrict__ Cl,
              int N, int K, size_t sA, size_t sB, size_t sC)
{
    extern __shared__ __align__(128) char dynsmem[];
    const int tid  = threadIdx.x;
    const int bz   = blockIdx.z;
    const int bm   = blockIdx.y * 128;
    const int bn   = blockIdx.x * 256;
    const int wid  = tid >> 5;
    const int lane = tid & 31;
    const int wm   = (wid >> 2) * 64;
    const int wn   = (wid & 3) * 64;

    const uint32_t sb = smem_u32(dynsmem);

    const __half* pA1 = A1 + (size_t)bz * sA + (size_t)bm * K;
    const __half* pA2 = (MODE != 3) ? A2 + (size_t)bz * sA + (size_t)bm * K : nullptr;
    const __half* pB1 = B1 + (size_t)bz * sB + (size_t)bn * K;
    const __half* pB2 = (MODE != 2) ? B2 + (size_t)bz * sB + (size_t)bn * K : nullptr;

    float acc[4][8][4];
    #pragma unroll
    for (int i = 0; i < 4; i++)
        #pragma unroll
        for (int j = 0; j < 8; j++)
            #pragma unroll
            for (int r = 0; r < 4; r++) acc[i][j][r] = 0.0f;

    const int nk = K >> 6;

    {
        load_tileA(sb, pA1, K, 0, tid);
        if (MODE != 3) load_tileA(sb + ATILEB, pA2, K, 0, tid);
        load_tileB(sb + 2*ATILEB, pB1, K, 0, tid);
        if (MODE != 2) load_tileB(sb + 2*ATILEB + BTILEB, pB2, K, 0, tid);
        asm volatile("cp.async.commit_group;" ::: "memory");
    }

    const uint32_t rowoff = (uint32_t)(lane & 15) * ROWB;
    const int      key    = lane & 7;
    const int      cbase  = lane >> 4;

    for (int c = 0; c < nk; ++c) {
        asm volatile("cp.async.wait_group 0;" ::: "memory");
        __syncthreads();

        if (c + 1 < nk) {
            uint32_t st = sb + (uint32_t)((c + 1) & 1) * STAGEB;
            int k0 = (c + 1) << 6;
            load_tileA(st, pA1, K, k0, tid);
            if (MODE != 3) load_tileA(st + ATILEB, pA2, K, k0, tid);
            load_tileB(st + 2*ATILEB, pB1, K, k0, tid);
            if (MODE != 2) load_tileB(st + 2*ATILEB + BTILEB, pB2, K, k0, tid);
            asm volatile("cp.async.commit_group;" ::: "memory");
        }

        const uint32_t st = sb + (uint32_t)(c & 1) * STAGEB;
        const uint32_t aH = st + (uint32_t)wm * ROWB + rowoff;
        const uint32_t aL = aH + ATILEB;
        const uint32_t bH = st + 2*ATILEB + (uint32_t)wn * ROWB + rowoff;
        const uint32_t bL = bH + BTILEB;

        #pragma unroll
        for (int kk = 0; kk < 4; kk++) {
            const uint32_t sw = (uint32_t)(((kk*2 + cbase) ^ key) << 4);
            uint32_t a1[4][4], a2[4][4], b1[4][4], b2[4][4];
            #pragma unroll
            for (int h = 0; h < 4; h++) ldmx4(b1[h], bH + (uint32_t)h * (16 * ROWB) + sw);
            #pragma unroll
            for (int mt = 0; mt < 4; mt++) ldmx4(a1[mt], aH + (uint32_t)mt * (16 * ROWB) + sw);
            if (MODE != 3) {
                #pragma unroll
                for (int mt = 0; mt < 4; mt++) ldmx4(a2[mt], aL + (uint32_t)mt * (16 * ROWB) + sw);
            }
            if (MODE != 2) {
                #pragma unroll
                for (int h = 0; h < 4; h++) ldmx4(b2[h], bL + (uint32_t)h * (16 * ROWB) + sw);
            }

            // term 1: A1 x B1 (32 independent MMAs)
            #pragma unroll
            for (int mt = 0; mt < 4; mt++)
                #pragma unroll
                for (int nt = 0; nt < 8; nt++) {
                    const int g = nt >> 1, s = nt & 1;
                    mma16816(acc[mt][nt], a1[mt], b1[g][s], b1[g][s + 2]);
                }
            // term 2: A2 x B1 (modes 1,2)
            if (MODE != 3) {
                #pragma unroll
                for (int mt = 0; mt < 4; mt++)
                    #pragma unroll
                    for (int nt = 0; nt < 8; nt++) {
                        const int g = nt >> 1, s = nt & 1;
                        mma16816(acc[mt][nt], a2[mt], b1[g][s], b1[g][s + 2]);
                    }
            }
            // term 3: A1 x B2 (modes 1,3)
            if (MODE != 2) {
                #pragma unroll
                for (int mt = 0; mt < 4; mt++)
                    #pragma unroll
                    for (int nt = 0; nt < 8; nt++) {
                        const int g = nt >> 1, s = nt & 1;
                        mma16816(acc[mt][nt], a1[mt], b2[g][s], b2[g][s + 2]);
                    }
            }
        }
    }

    // ---------------- epilogue ----------------
    const int r0 = lane >> 2;
    const int c0 = (lane & 3) * 2;

    #pragma unroll
    for (int mt = 0; mt < 4; mt++) {
        #pragma unroll
        for (int half_ = 0; half_ < 2; half_++) {
            const size_t grow = (size_t)(bm + wm + mt * 16 + r0 + half_ * 8);
            #pragma unroll
            for (int nt = 0; nt < 8; nt++) {
                const int gcol = bn + wn + nt * 8 + c0;
                float v0 = acc[mt][nt][half_ * 2 + 0];
                float v1 = acc[mt][nt][half_ * 2 + 1];

                if (MODE == 1) {
                    v0 += bias[gcol];
                    v1 += bias[gcol + 1];
                    __half h0, l0, h1, l1;
                    split2h(v0, h0, l0); split2h(v1, h1, l1);
                    uint32_t ph = ((uint32_t)__half_as_ushort(h1) << 16) | __half_as_ushort(h0);
                    uint32_t pl = ((uint32_t)__half_as_ushort(l1) << 16) | __half_as_ushort(l0);
                    *(uint32_t*)(Ch + (size_t)bz * sC + grow * N + gcol) = ph;
                    *(uint32_t*)(Cl + (size_t)bz * sC + grow * N + gcol) = pl;
                } else if (MODE == 2) {
                    int2 mm = *(const int2*)(mask + (size_t)bz * sC + grow * N + gcol);
                    float2 vv;
                    vv.x = v0 + (mm.x ? 0.0f : NEGV);
                    vv.y = v1 + (mm.y ? 0.0f : NEGV);
                    *(float2*)(Cf + (size_t)bz * sC + grow * N + gcol) = vv;
                } else {
                    *(float2*)(Cf + (size_t)bz * sC + grow * N + gcol) = make_float2(v0, v1);
                }
            }
        }
    }
}

// ------------------------- elementwise split fp32 -> (hi,lo) fp16 -------------------------
__global__ __launch_bounds__(256)
void split_kernel(const float* __restrict__ x, __half* __restrict__ hi,
                  __half* __restrict__ lo, size_t n)
{
    size_t i = ((size_t)blockIdx.x * 256 + threadIdx.x) * 4;
    if (i >= n) return;
    float4 v = *(const float4*)(x + i);
    float f[4] = {v.x, v.y, v.z, v.w};
    uint32_t ph[2], pl[2];
    #pragma unroll
    for (int j = 0; j < 2; j++) {
        __half h0, l0, h1, l1;
        split2h(f[2*j], h0, l0); split2h(f[2*j+1], h1, l1);
        ph[j] = ((uint32_t)__half_as_ushort(h1) << 16) | __half_as_ushort(h0);
        pl[j] = ((uint32_t)__half_as_ushort(l1) << 16) | __half_as_ushort(l0);
    }
    *(uint2*)(hi + i) = make_uint2(ph[0], ph[1]);
    *(uint2*)(lo + i) = make_uint2(pl[0], pl[1]);
}

// ---- fused: memories fp32 -> single fp16 row-major AND split-fp16 transposed ----
__global__ __launch_bounds__(256)
void mem_prep_kernel(const float* __restrict__ src,
                     __half* __restrict__ m1,
                     __half* __restrict__ th, __half* __restrict__ tl,
                     int R, int C)
{
    __shared__ float t[32][33];
    const int z = blockIdx.z;
    src += (size_t)z * R * C;
    m1  += (size_t)z * R * C;
    th  += (size_t)z * R * C;  tl += (size_t)z * R * C;
    const int c0 = blockIdx.x * 32, r0 = blockIdx.y * 32;
    const int tx = threadIdx.x, ty = threadIdx.y;

    #pragma unroll
    for (int i = 0; i < 4; i++) {
        const int r = r0 + ty + 8*i;
        float v = src[(size_t)r * C + c0 + tx];
        t[ty + 8*i][tx] = v;
        m1[(size_t)r * C + c0 + tx] = __float2half_rn(v);
    }
    __syncthreads();
    #pragma unroll
    for (int i = 0; i < 4; i++) {
        const int c = c0 + ty + 8*i;
        float v = t[tx][ty + 8*i];
        __half h, l;
        split2h(v, h, l);
        th[(size_t)c * R + r0 + tx] = h;
        tl[(size_t)c * R + r0 + tx] = l;
    }
}

// ------------------------- row softmax over LM, writes single-fp16 weights -------------------------
__global__ __launch_bounds__(256)
void softmax_kernel(const float* __restrict__ x, __half* __restrict__ w)
{
    const float* row = x + (size_t)blockIdx.x * LM;
    __half* rw = w + (size_t)blockIdx.x * LM;
    const int t = threadIdx.x;
    __shared__ float smax[8], ssum[8];

    float v[8];
    float m = -3.0e38f;
    #pragma unroll
    for (int i = 0; i < 8; i++) { v[i] = row[t + i*256]; m = fmaxf(m, v[i]); }
    #pragma unroll
    for (int o = 16; o > 0; o >>= 1) m = fmaxf(m, __shfl_xor_sync(0xFFFFFFFFu, m, o));
    if ((t & 31) == 0) smax[t >> 5] = m;
    __syncthreads();
    m = smax[0];
    #pragma unroll
    for (int i = 1; i < 8; i++) m = fmaxf(m, smax[i]);

    float s = 0.0f;
    #pragma unroll
    for (int i = 0; i < 8; i++) { v[i] = expf(v[i] - m); s += v[i]; }
    #pragma unroll
    for (int o = 16; o > 0; o >>= 1) s += __shfl_xor_sync(0xFFFFFFFFu, s, o);
    if ((t & 31) == 0) ssum[t >> 5] = s;
    __syncthreads();
    s = 0.0f;
    #pragma unroll
    for (int i = 0; i < 8; i++) s += ssum[i];
    const float inv = 1.0f / s;

    #pragma unroll
    for (int i = 0; i < 8; i++)
        rw[t + i*256] = __float2half_rn(v[i] * inv);
}

// ------------------------- launch -------------------------
extern "C" void kernel_launch(void* const* d_in, const int* in_sizes, int n_in,
                              void* d_out, int out_size)
{
    (void)in_sizes; (void)n_in; (void)out_size;
    const float* query    = (const float*)d_in[0];
    const float* memories = (const float*)d_in[1];
    const int*   mask     = (const int*)d_in[2];
    const float* W        = (const float*)d_in[3];
    const float* bvec     = (const float*)d_in[4];
    float*       out      = (float*)d_out;

    __half *qryh, *qryl, *Wh, *Wl, *qh, *ql, *mh, *mTh, *mTl, *w;
    float *logits;
    cudaGetSymbolAddress((void**)&qryh, g_qryh);  cudaGetSymbolAddress((void**)&qryl, g_qryl);
    cudaGetSymbolAddress((void**)&Wh,   g_Wh);    cudaGetSymbolAddress((void**)&Wl,   g_Wl);
    cudaGetSymbolAddress((void**)&qh,   g_qh);    cudaGetSymbolAddress((void**)&ql,   g_ql);
    cudaGetSymbolAddress((void**)&mh,   g_mh);
    cudaGetSymbolAddress((void**)&mTh,  g_mTh);   cudaGetSymbolAddress((void**)&mTl,  g_mTl);
    cudaGetSymbolAddress((void**)&w,    g_w);
    cudaGetSymbolAddress((void**)&logits, g_logits);

    const int SMEM = NSTAGE * STAGEB;   // 196608 B
    cudaFuncSetAttribute(gemm_mma<1>, cudaFuncAttributeMaxDynamicSharedMemorySize, SMEM);
    cudaFuncSetAttribute(gemm_mma<2>, cudaFuncAttributeMaxDynamicSharedMemorySize, SMEM);
    cudaFuncSetAttribute(gemm_mma<3>, cudaFuncAttributeMaxDynamicSharedMemorySize, SMEM);

    const size_t nQ = (size_t)BB * LQ * DD;
    const size_t nW = (size_t)DD * DD;

    // 0) prep: split query + W (fp16 pairs); memories -> fp16 single + transposed split
    split_kernel<<<(unsigned)(nQ / 1024), 256>>>(query, qryh, qryl, nQ);
    split_kernel<<<(unsigned)(nW / 1024), 256>>>(W,     Wh,   Wl,   nW);
    mem_prep_kernel<<<dim3(DD/32, LM/32, BB), dim3(32, 8)>>>(memories, mh, mTh, mTl, LM, DD);

    // 1) q = query @ W^T + b  (3-term) -> split fp16 (qh, ql)
    gemm_mma<1><<<dim3(DD/256, (BB*LQ)/128, 1), 256, SMEM>>>(
        qryh, qryl, Wh, Wl, bvec, nullptr, nullptr, qh, ql,
        DD, DD, (size_t)0, (size_t)0, (size_t)0);

    // 2) logits = (qh+ql) @ mh^T + mask  (2-term) -> fp32
    gemm_mma<2><<<dim3(LM/256, LQ/128, BB), 256, SMEM>>>(
        qh, ql, mh, nullptr, nullptr, mask, logits, nullptr, nullptr,
        LM, DD, (size_t)LQ*DD, (size_t)LM*DD, (size_t)LQ*LM);

    // 3) softmax -> single fp16 weights
    softmax_kernel<<<BB*LQ, 256>>>(logits, w);

    // 4) out = w @ (mTh+mTl)^T  (2-term) -> fp32
    gemm_mma<3><<<dim3(DD/256, LQ/128, BB), 256, SMEM>>>(
        w, nullptr, mTh, mTl, nullptr, nullptr, out, nullptr, nullptr,
        DD, LM, (size_t)LQ*LM, (size_t)DD*LM, (size_t)LQ*DD);
}

// round 14
// speedup vs baseline: 2.0472x; 1.0070x over previous
#include <cuda_runtime.h>
#include <cuda_fp16.h>
#include <cstdint>

#define BB 8
#define LQ 2048
#define LM 2048
#define DD 1024
#define NEGV (-1000000.0f)

// ------------------------- scratch (device globals) -------------------------
__device__ __half g_qryh[(size_t)BB*LQ*DD], g_qryl[(size_t)BB*LQ*DD];
__device__ __half g_Wh[(size_t)DD*DD],      g_Wl[(size_t)DD*DD];
__device__ __half g_qh[(size_t)BB*LQ*DD],   g_ql[(size_t)BB*LQ*DD];
__device__ __half g_mh[(size_t)BB*LM*DD],   g_ml[(size_t)BB*LM*DD];  // memories split, K-major
__device__ __half g_mTh[(size_t)BB*DD*LM];                            // transposed, single fp16
__device__ float  g_logits[(size_t)BB*LQ*LM];
__device__ __half g_w[(size_t)BB*LQ*LM];                              // softmax weights, fp16

// ------------------------- helpers -------------------------
__device__ __forceinline__ uint32_t smem_u32(const void* p) {
    uint32_t a;
    asm("{ .reg .u64 t; cvta.to.shared.u64 t, %1; cvt.u32.u64 %0, t; }" : "=r"(a) : "l"(p));
    return a;
}
__device__ __forceinline__ void cp16(uint32_t s, const void* g) {
    asm volatile("cp.async.cg.shared.global [%0], [%1], 16;" :: "r"(s), "l"(g));
}
__device__ __forceinline__ void ldmx4(uint32_t* r, uint32_t a) {
    asm volatile("ldmatrix.sync.aligned.m8n8.x4.shared.b16 {%0,%1,%2,%3}, [%4];"
                 : "=r"(r[0]), "=r"(r[1]), "=r"(r[2]), "=r"(r[3]) : "r"(a));
}
__device__ __forceinline__ void mma16816(float* c, const uint32_t* a, uint32_t b0, uint32_t b1) {
    asm volatile(
        "mma.sync.aligned.m16n8k16.row.col.f32.f16.f16.f32 "
        "{%0,%1,%2,%3}, {%4,%5,%6,%7}, {%8,%9}, {%0,%1,%2,%3};"
        : "+f"(c[0]), "+f"(c[1]), "+f"(c[2]), "+f"(c[3])
        : "r"(a[0]), "r"(a[1]), "r"(a[2]), "r"(a[3]), "r"(b0), "r"(b1));
}
__device__ __forceinline__ void split2h(float v, __half& h, __half& l) {
    h = __float2half_rn(v);
    l = __float2half_rn(v - __half2float(h));
}

// ------------------------- fp16 split mma.sync GEMM (NT, K-major) -------------------------
// CTA tile 128(M) x 256(N), 256 threads = 8 warps (2x4), warp tile 64x64.
// K-chunk 64, XOR-swizzled 128B SMEM rows, 2 stages, term-major MMA order.
// MODE 1: C=(A1+A2)(B1+B2)^T 3-term, +bias, out split-fp16 (Ch,Cl)
// MODE 2: C=(A1+A2)(B1+B2)^T 3-term, +mask NEG, out fp32
// MODE 3: C=A1·B1^T          1-term, plain, out fp32

#define ROWB 128
#define ATILEB (128 * ROWB)            // 16384
#define BTILEB (256 * ROWB)            // 32768
#define STAGEB (2*ATILEB + 2*BTILEB)   // 98304 (fixed layout; modes use subsets)
#define NSTAGE 2

__device__ __forceinline__ void load_tileA(uint32_t st, const __half* g, int K, int k0, int tid) {
    #pragma unroll
    for (int p = 0; p < 4; p++) {
        int idx = p * 256 + tid;
        int row = idx >> 3, c = idx & 7;
        cp16(st + (uint32_t)row * ROWB + (uint32_t)((c ^ (row & 7)) << 4),
             g + (size_t)row * K + k0 + c * 8);
    }
}
__device__ __forceinline__ void load_tileB(uint32_t st, const __half* g, int K, int k0, int tid) {
    #pragma unroll
    for (int p = 0; p < 8; p++) {
        int idx = p * 256 + tid;
        int row = idx >> 3, c = idx & 7;
        cp16(st + (uint32_t)row * ROWB + (uint32_t)((c ^ (row & 7)) << 4),
             g + (size_t)row * K + k0 + c * 8);
    }
}

template<int MODE>
__global__ __launch_bounds__(256)
void gemm_mma(const __half* __restrict__ A1, const __half* __restrict__ A2,
              const __half* __restrict__ B1, const __half* __restrict__ B2,
              const float* __restrict__ bias, const int* __restrict__ mask,
              float* __restrict__ Cf, __half* __restrict__ Ch, __half* __restrict__ Cl,
              int N, int K, size_t sA, size_t sB, size_t sC)
{
    extern __shared__ __align__(128) char dynsmem[];
    const int tid  = threadIdx.x;
    const int bz   = blockIdx.z;
    const int bm   = blockIdx.y * 128;
    const int bn   = blockIdx.x * 256;
    const int wid  = tid >> 5;
    const int lane = tid & 31;
    const int wm   = (wid >> 2) * 64;
    const int wn   = (wid & 3) * 64;

    const uint32_t sb = smem_u32(dynsmem);

    const __half* pA1 = A1 + (size_t)bz * sA + (size_t)bm * K;
    const __half* pA2 = (MODE != 3) ? A2 + (size_t)bz * sA + (size_t)bm * K : nullptr;
    const __half* pB1 = B1 + (size_t)bz * sB + (size_t)bn * K;
    const __half* pB2 = (MODE != 3) ? B2 + (size_t)bz * sB + (size_t)bn * K : nullptr;

    float acc[4][8][4];
    #pragma unroll
    for (int i = 0; i < 4; i++)
        #pragma unroll
        for (int j = 0; j < 8; j++)
            #pragma unroll
            for (int r = 0; r < 4; r++) acc[i][j][r] = 0.0f;

    const int nk = K >> 6;

    {
        load_tileA(sb, pA1, K, 0, tid);
        if (MODE != 3) load_tileA(sb + ATILEB, pA2, K, 0, tid);
        load_tileB(sb + 2*ATILEB, pB1, K, 0, tid);
        if (MODE != 3) load_tileB(sb + 2*ATILEB + BTILEB, pB2, K, 0, tid);
        asm volatile("cp.async.commit_group;" ::: "memory");
    }

    const uint32_t rowoff = (uint32_t)(lane & 15) * ROWB;
    const int      key    = lane & 7;
    const int      cbase  = lane >> 4;

    for (int c = 0; c < nk; ++c) {
        asm volatile("cp.async.wait_group 0;" ::: "memory");
        __syncthreads();

        if (c + 1 < nk) {
            uint32_t st = sb + (uint32_t)((c + 1) & 1) * STAGEB;
            int k0 = (c + 1) << 6;
            load_tileA(st, pA1, K, k0, tid);
            if (MODE != 3) load_tileA(st + ATILEB, pA2, K, k0, tid);
            load_tileB(st + 2*ATILEB, pB1, K, k0, tid);
            if (MODE != 3) load_tileB(st + 2*ATILEB + BTILEB, pB2, K, k0, tid);
            asm volatile("cp.async.commit_group;" ::: "memory");
        }

        const uint32_t st = sb + (uint32_t)(c & 1) * STAGEB;
        const uint32_t aH = st + (uint32_t)wm * ROWB + rowoff;
        const uint32_t aL = aH + ATILEB;
        const uint32_t bH = st + 2*ATILEB + (uint32_t)wn * ROWB + rowoff;
        const uint32_t bL = bH + BTILEB;

        #pragma unroll
        for (int kk = 0; kk < 4; kk++) {
            const uint32_t sw = (uint32_t)(((kk*2 + cbase) ^ key) << 4);
            uint32_t a1[4][4], a2[4][4], b1[4][4], b2[4][4];
            #pragma unroll
            for (int h = 0; h < 4; h++) ldmx4(b1[h], bH + (uint32_t)h * (16 * ROWB) + sw);
            #pragma unroll
            for (int mt = 0; mt < 4; mt++) ldmx4(a1[mt], aH + (uint32_t)mt * (16 * ROWB) + sw);
            if (MODE != 3) {
                #pragma unroll
                for (int mt = 0; mt < 4; mt++) ldmx4(a2[mt], aL + (uint32_t)mt * (16 * ROWB) + sw);
                #pragma unroll
                for (int h = 0; h < 4; h++) ldmx4(b2[h], bL + (uint32_t)h * (16 * ROWB) + sw);
            }

            // term 1: A1 x B1 (32 independent MMAs)
            #pragma unroll
            for (int mt = 0; mt < 4; mt++)
                #pragma unroll
                for (int nt = 0; nt < 8; nt++) {
                    const int g = nt >> 1, s = nt & 1;
                    mma16816(acc[mt][nt], a1[mt], b1[g][s], b1[g][s + 2]);
                }
            if (MODE != 3) {
                // term 2: A2 x B1
                #pragma unroll
                for (int mt = 0; mt < 4; mt++)
                    #pragma unroll
                    for (int nt = 0; nt < 8; nt++) {
                        const int g = nt >> 1, s = nt & 1;
                        mma16816(acc[mt][nt], a2[mt], b1[g][s], b1[g][s + 2]);
                    }
                // term 3: A1 x B2
                #pragma unroll
                for (int mt = 0; mt < 4; mt++)
                    #pragma unroll
                    for (int nt = 0; nt < 8; nt++) {
                        const int g = nt >> 1, s = nt & 1;
                        mma16816(acc[mt][nt], a1[mt], b2[g][s], b2[g][s + 2]);
                    }
            }
        }
    }

    // ---------------- epilogue ----------------
    const int r0 = lane >> 2;
    const int c0 = (lane & 3) * 2;

    #pragma unroll
    for (int mt = 0; mt < 4; mt++) {
        #pragma unroll
        for (int half_ = 0; half_ < 2; half_++) {
            const size_t grow = (size_t)(bm + wm + mt * 16 + r0 + half_ * 8);
            #pragma unroll
            for (int nt = 0; nt < 8; nt++) {
                const int gcol = bn + wn + nt * 8 + c0;
                float v0 = acc[mt][nt][half_ * 2 + 0];
                float v1 = acc[mt][nt][half_ * 2 + 1];

                if (MODE == 1) {
                    v0 += bias[gcol];
                    v1 += bias[gcol + 1];
                    __half h0, l0, h1, l1;
                    split2h(v0, h0, l0); split2h(v1, h1, l1);
                    uint32_t ph = ((uint32_t)__half_as_ushort(h1) << 16) | __half_as_ushort(h0);
                    uint32_t pl = ((uint32_t)__half_as_ushort(l1) << 16) | __half_as_ushort(l0);
                    *(uint32_t*)(Ch + (size_t)bz * sC + grow * N + gcol) = ph;
                    *(uint32_t*)(Cl + (size_t)bz * sC + grow * N + gcol) = pl;
                } else if (MODE == 2) {
                    int2 mm = *(const int2*)(mask + (size_t)bz * sC + grow * N + gcol);
                    float2 vv;
                    vv.x = v0 + (mm.x ? 0.0f : NEGV);
                    vv.y = v1 + (mm.y ? 0.0f : NEGV);
                    *(float2*)(Cf + (size_t)bz * sC + grow * N + gcol) = vv;
                } else {
                    *(float2*)(Cf + (size_t)bz * sC + grow * N + gcol) = make_float2(v0, v1);
                }
            }
        }
    }
}

// ------------------------- elementwise split fp32 -> (hi,lo) fp16 -------------------------
__global__ __launch_bounds__(256)
void split_kernel(const float* __restrict__ x, __half* __restrict__ hi,
                  __half* __restrict__ lo, size_t n)
{
    size_t i = ((size_t)blockIdx.x * 256 + threadIdx.x) * 4;
    if (i >= n) return;
    float4 v = *(const float4*)(x + i);
    float f[4] = {v.x, v.y, v.z, v.w};
    uint32_t ph[2], pl[2];
    #pragma unroll
    for (int j = 0; j < 2; j++) {
        __half h0, l0, h1, l1;
        split2h(f[2*j], h0, l0); split2h(f[2*j+1], h1, l1);
        ph[j] = ((uint32_t)__half_as_ushort(h1) << 16) | __half_as_ushort(h0);
        pl[j] = ((uint32_t)__half_as_ushort(l1) << 16) | __half_as_ushort(l0);
    }
    *(uint2*)(hi + i) = make_uint2(ph[0], ph[1]);
    *(uint2*)(lo + i) = make_uint2(pl[0], pl[1]);
}

// ---- fused: memories fp32 -> split-fp16 row-major (mh,ml) AND single-fp16 transposed ----
__global__ __launch_bounds__(256)
void mem_prep_kernel(const float* __restrict__ src,
                     __half* __restrict__ mh, __half* __restrict__ ml,
                     __half* __restrict__ th,
                     int R, int C)
{
    __shared__ float t[32][33];
    const int z = blockIdx.z;
    src += (size_t)z * R * C;
    mh  += (size_t)z * R * C;  ml += (size_t)z * R * C;
    th  += (size_t)z * R * C;
    const int c0 = blockIdx.x * 32, r0 = blockIdx.y * 32;
    const int tx = threadIdx.x, ty = threadIdx.y;

    #pragma unroll
    for (int i = 0; i < 4; i++) {
        const int r = r0 + ty + 8*i;
        float v = src[(size_t)r * C + c0 + tx];
        t[ty + 8*i][tx] = v;
        __half h, l;
        split2h(v, h, l);
        mh[(size_t)r * C + c0 + tx] = h;
        ml[(size_t)r * C + c0 + tx] = l;
    }
    __syncthreads();
    #pragma unroll
    for (int i = 0; i < 4; i++) {
        const int c = c0 + ty + 8*i;
        float v = t[tx][ty + 8*i];
        th[(size_t)c * R + r0 + tx] = __float2half_rn(v);
    }
}

// ------------------------- row softmax over LM, writes single-fp16 weights -------------------------
__global__ __launch_bounds__(256)
void softmax_kernel(const float* __restrict__ x, __half* __restrict__ w)
{
    const float* row = x + (size_t)blockIdx.x * LM;
    __half* rw = w + (size_t)blockIdx.x * LM;
    const int t = threadIdx.x;
    __shared__ float smax[8], ssum[8];

    float v[8];
    float m = -3.0e38f;
    #pragma unroll
    for (int i = 0; i < 8; i++) { v[i] = row[t + i*256]; m = fmaxf(m, v[i]); }
    #pragma unroll
    for (int o = 16; o > 0; o >>= 1) m = fmaxf(m, __shfl_xor_sync(0xFFFFFFFFu, m, o));
    if ((t & 31) == 0) smax[t >> 5] = m;
    __syncthreads();
    m = smax[0];
    #pragma unroll
    for (int i = 1; i < 8; i++) m = fmaxf(m, smax[i]);

    float s = 0.0f;
    #pragma unroll
    for (int i = 0; i < 8; i++) { v[i] = expf(v[i] - m); s += v[i]; }
    #pragma unroll
    for (int o = 16; o > 0; o >>= 1) s += __shfl_xor_sync(0xFFFFFFFFu, s, o);
    if ((t & 31) == 0) ssum[t >> 5] = s;
    __syncthreads();
    s = 0.0f;
    #pragma unroll
    for (int i = 0; i < 8; i++) s += ssum[i];
    const float inv = 1.0f / s;

    #pragma unroll
    for (int i = 0; i < 8; i++)
        rw[t + i*256] = __float2half_rn(v[i] * inv);
}

// ------------------------- launch -------------------------
extern "C" void kernel_launch(void* const* d_in, const int* in_sizes, int n_in,
                              void* d_out, int out_size)
{
    (void)in_sizes; (void)n_in; (void)out_size;
    const float* query    = (const float*)d_in[0];
    const float* memories = (const float*)d_in[1];
    const int*   mask     = (const int*)d_in[2];
    const float* W        = (const float*)d_in[3];
    const float* bvec     = (const float*)d_in[4];
    float*       out      = (float*)d_out;

    __half *qryh, *qryl, *Wh, *Wl, *qh, *ql, *mh, *ml, *mTh, *w;
    float *logits;
    cudaGetSymbolAddress((void**)&qryh, g_qryh);  cudaGetSymbolAddress((void**)&qryl, g_qryl);
    cudaGetSymbolAddress((void**)&Wh,   g_Wh);    cudaGetSymbolAddress((void**)&Wl,   g_Wl);
    cudaGetSymbolAddress((void**)&qh,   g_qh);    cudaGetSymbolAddress((void**)&ql,   g_ql);
    cudaGetSymbolAddress((void**)&mh,   g_mh);    cudaGetSymbolAddress((void**)&ml,   g_ml);
    cudaGetSymbolAddress((void**)&mTh,  g_mTh);
    cudaGetSymbolAddress((void**)&w,    g_w);
    cudaGetSymbolAddress((void**)&logits, g_logits);

    const int SMEM = NSTAGE * STAGEB;   // 196608 B
    cudaFuncSetAttribute(gemm_mma<1>, cudaFuncAttributeMaxDynamicSharedMemorySize, SMEM);
    cudaFuncSetAttribute(gemm_mma<2>, cudaFuncAttributeMaxDynamicSharedMemorySize, SMEM);
    cudaFuncSetAttribute(gemm_mma<3>, cudaFuncAttributeMaxDynamicSharedMemorySize, SMEM);

    const size_t nQ = (size_t)BB * LQ * DD;
    const size_t nW = (size_t)DD * DD;

    // 0) prep: split query + W; memories -> row-major split (mh,ml) + transposed single (mTh)
    split_kernel<<<(unsigned)(nQ / 1024), 256>>>(query, qryh, qryl, nQ);
    split_kernel<<<(unsigned)(nW / 1024), 256>>>(W,     Wh,   Wl,   nW);
    mem_prep_kernel<<<dim3(DD/32, LM/32, BB), dim3(32, 8)>>>(memories, mh, ml, mTh, LM, DD);

    // 1) q = query @ W^T + b  (3-term) -> split fp16 (qh, ql)
    gemm_mma<1><<<dim3(DD/256, (BB*LQ)/128, 1), 256, SMEM>>>(
        qryh, qryl, Wh, Wl, bvec, nullptr, nullptr, qh, ql,
        DD, DD, (size_t)0, (size_t)0, (size_t)0);

    // 2) logits = (qh+ql) @ (mh+ml)^T + mask  (3-term) -> fp32
    gemm_mma<2><<<dim3(LM/256, LQ/128, BB), 256, SMEM>>>(
        qh, ql, mh, ml, nullptr, mask, logits, nullptr, nullptr,
        LM, DD, (size_t)LQ*DD, (size_t)LM*DD, (size_t)LQ*LM);

    // 3) softmax -> single fp16 weights
    softmax_kernel<<<BB*LQ, 256>>>(logits, w);

    // 4) out = w @ mTh^T  (1-term) -> fp32
    gemm_mma<3><<<dim3(DD/256, LQ/128, BB), 256, SMEM>>>(
        w, nullptr, mTh, nullptr, nullptr, nullptr, out, nullptr, nullptr,
        DD, LM, (size_t)LQ*LM, (size_t)DD*LM, (size_t)LQ*DD);
}

// round 15
// speedup vs baseline: 2.0518x; 1.0022x over previous
#include <cuda_runtime.h>
#include <cuda_fp16.h>
#include <cstdint>

#define BB 8
#define LQ 2048
#define LM 2048
#define DD 1024
#define NEGV (-1000000.0f)

// ------------------------- scratch (device globals) -------------------------
__device__ __half g_qryh[(size_t)BB*LQ*DD], g_qryl[(size_t)BB*LQ*DD];
__device__ __half g_Wh[(size_t)DD*DD],      g_Wl[(size_t)DD*DD];
__device__ __half g_qh[(size_t)BB*LQ*DD],   g_ql[(size_t)BB*LQ*DD];
__device__ __half g_mh[(size_t)BB*LM*DD],   g_ml[(size_t)BB*LM*DD];  // memories split, K-major
__device__ __half g_mTh[(size_t)BB*DD*LM];                            // transposed, single fp16
__device__ float  g_logits[(size_t)BB*LQ*LM];
__device__ __half g_w[(size_t)BB*LQ*LM];                              // softmax weights, fp16

// ------------------------- helpers -------------------------
__device__ __forceinline__ uint32_t smem_u32(const void* p) {
    uint32_t a;
    asm("{ .reg .u64 t; cvta.to.shared.u64 t, %1; cvt.u32.u64 %0, t; }" : "=r"(a) : "l"(p));
    return a;
}
__device__ __forceinline__ void cp16(uint32_t s, const void* g) {
    asm volatile("cp.async.cg.shared.global [%0], [%1], 16;" :: "r"(s), "l"(g));
}
__device__ __forceinline__ void ldmx4(uint32_t* r, uint32_t a) {
    asm volatile("ldmatrix.sync.aligned.m8n8.x4.shared.b16 {%0,%1,%2,%3}, [%4];"
                 : "=r"(r[0]), "=r"(r[1]), "=r"(r[2]), "=r"(r[3]) : "r"(a));
}
// fp32-accumulator HMMA
__device__ __forceinline__ void mma16816(float* c, const uint32_t* a, uint32_t b0, uint32_t b1) {
    asm volatile(
        "mma.sync.aligned.m16n8k16.row.col.f32.f16.f16.f32 "
        "{%0,%1,%2,%3}, {%4,%5,%6,%7}, {%8,%9}, {%0,%1,%2,%3};"
        : "+f"(c[0]), "+f"(c[1]), "+f"(c[2]), "+f"(c[3])
        : "r"(a[0]), "r"(a[1]), "r"(a[2]), "r"(a[3]), "r"(b0), "r"(b1));
}
// fp16-accumulator HMMA (D,C = 2 packed half2 regs) — rate experiment
__device__ __forceinline__ void mma16816h(uint32_t* c, const uint32_t* a, uint32_t b0, uint32_t b1) {
    asm volatile(
        "mma.sync.aligned.m16n8k16.row.col.f16.f16.f16.f16 "
        "{%0,%1}, {%2,%3,%4,%5}, {%6,%7}, {%0,%1};"
        : "+r"(c[0]), "+r"(c[1])
        : "r"(a[0]), "r"(a[1]), "r"(a[2]), "r"(a[3]), "r"(b0), "r"(b1));
}
__device__ __forceinline__ void split2h(float v, __half& h, __half& l) {
    h = __float2half_rn(v);
    l = __float2half_rn(v - __half2float(h));
}

// ------------------------- fp16 split mma.sync GEMM (NT, K-major) -------------------------
// CTA tile 128(M) x 256(N), 256 threads = 8 warps (2x4), warp tile 64x64.
// K-chunk 64, XOR-swizzled 128B SMEM rows, 2 stages, term-major MMA order.
// MODE 1: main term fp32-acc; corrections (A2·B1, A1·B2) f16-acc; +bias; out split-fp16
// MODE 2: same accumulation scheme; +mask NEG; out fp32
// MODE 3: C=A1·B1^T 1-term fp32-acc, plain, out fp32

#define ROWB 128
#define ATILEB (128 * ROWB)            // 16384
#define BTILEB (256 * ROWB)            // 32768
#define STAGEB (2*ATILEB + 2*BTILEB)   // 98304 (fixed layout; modes use subsets)
#define NSTAGE 2

__device__ __forceinline__ void load_tileA(uint32_t st, const __half* g, int K, int k0, int tid) {
    #pragma unroll
    for (int p = 0; p < 4; p++) {
        int idx = p * 256 + tid;
        int row = idx >> 3, c = idx & 7;
        cp16(st + (uint32_t)row * ROWB + (uint32_t)((c ^ (row & 7)) << 4),
             g + (size_t)row * K + k0 + c * 8);
    }
}
__device__ __forceinline__ void load_tileB(uint32_t st, const __half* g, int K, int k0, int tid) {
    #pragma unroll
    for (int p = 0; p < 8; p++) {
        int idx = p * 256 + tid;
        int row = idx >> 3, c = idx & 7;
        cp16(st + (uint32_t)row * ROWB + (uint32_t)((c ^ (row & 7)) << 4),
             g + (size_t)row * K + k0 + c * 8);
    }
}

template<int MODE>
__global__ __launch_bounds__(256)
void gemm_mma(const __half* __restrict__ A1, const __half* __restrict__ A2,
              const __half* __restrict__ B1, const __half* __restrict__ B2,
              const float* __restrict__ bias, const int* __restrict__ mask,
              float* __restrict__ Cf, __half* __restrict__ Ch, __half* __restrict__ Cl,
              int N, int K, size_t sA, size_t sB, size_t sC)
{
    extern __shared__ __align__(128) char dynsmem[];
    const int tid  = threadIdx.x;
    const int bz   = blockIdx.z;
    const int bm   = blockIdx.y * 128;
    const int bn   = blockIdx.x * 256;
    const int wid  = tid >> 5;
    const int lane = tid & 31;
    const int wm   = (wid >> 2) * 64;
    const int wn   = (wid & 3) * 64;

    const uint32_t sb = smem_u32(dynsmem);

    const __half* pA1 = A1 + (size_t)bz * sA + (size_t)bm * K;
    const __half* pA2 = (MODE != 3) ? A2 + (size_t)bz * sA + (size_t)bm * K : nullptr;
    const __half* pB1 = B1 + (size_t)bz * sB + (size_t)bn * K;
    const __half* pB2 = (MODE != 3) ? B2 + (size_t)bz * sB + (size_t)bn * K : nullptr;

    float acc[4][8][4];
    #pragma unroll
    for (int i = 0; i < 4; i++)
        #pragma unroll
        for (int j = 0; j < 8; j++)
            #pragma unroll
            for (int r = 0; r < 4; r++) acc[i][j][r] = 0.0f;

    // f16 correction accumulators (modes 1,2): 2 packed half2 regs per tile
    uint32_t facc[4][8][2];
    if (MODE != 3) {
        #pragma unroll
        for (int i = 0; i < 4; i++)
            #pragma unroll
            for (int j = 0; j < 8; j++) { facc[i][j][0] = 0u; facc[i][j][1] = 0u; }
    }

    const int nk = K >> 6;

    {
        load_tileA(sb, pA1, K, 0, tid);
        if (MODE != 3) load_tileA(sb + ATILEB, pA2, K, 0, tid);
        load_tileB(sb + 2*ATILEB, pB1, K, 0, tid);
        if (MODE != 3) load_tileB(sb + 2*ATILEB + BTILEB, pB2, K, 0, tid);
        asm volatile("cp.async.commit_group;" ::: "memory");
    }

    const uint32_t rowoff = (uint32_t)(lane & 15) * ROWB;
    const int      key    = lane & 7;
    const int      cbase  = lane >> 4;

    for (int c = 0; c < nk; ++c) {
        asm volatile("cp.async.wait_group 0;" ::: "memory");
        __syncthreads();

        if (c + 1 < nk) {
            uint32_t st = sb + (uint32_t)((c + 1) & 1) * STAGEB;
            int k0 = (c + 1) << 6;
            load_tileA(st, pA1, K, k0, tid);
            if (MODE != 3) load_tileA(st + ATILEB, pA2, K, k0, tid);
            load_tileB(st + 2*ATILEB, pB1, K, k0, tid);
            if (MODE != 3) load_tileB(st + 2*ATILEB + BTILEB, pB2, K, k0, tid);
            asm volatile("cp.async.commit_group;" ::: "memory");
        }

        const uint32_t st = sb + (uint32_t)(c & 1) * STAGEB;
        const uint32_t aH = st + (uint32_t)wm * ROWB + rowoff;
        const uint32_t aL = aH + ATILEB;
        const uint32_t bH = st + 2*ATILEB + (uint32_t)wn * ROWB + rowoff;
        const uint32_t bL = bH + BTILEB;

        #pragma unroll
        for (int kk = 0; kk < 4; kk++) {
            const uint32_t sw = (uint32_t)(((kk*2 + cbase) ^ key) << 4);
            uint32_t a1[4][4], b1[4][4];
            #pragma unroll
            for (int h = 0; h < 4; h++) ldmx4(b1[h], bH + (uint32_t)h * (16 * ROWB) + sw);
            #pragma unroll
            for (int mt = 0; mt < 4; mt++) ldmx4(a1[mt], aH + (uint32_t)mt * (16 * ROWB) + sw);

            // term 1 (main): A1 x B1 -> fp32 acc (32 independent MMAs)
            #pragma unroll
            for (int mt = 0; mt < 4; mt++)
                #pragma unroll
                for (int nt = 0; nt < 8; nt++) {
                    const int g = nt >> 1, s = nt & 1;
                    mma16816(acc[mt][nt], a1[mt], b1[g][s], b1[g][s + 2]);
                }

            if (MODE != 3) {
                // term 2 (corr): A2 x B1 -> f16 acc (a2 loaded here, dead after)
                {
                    uint32_t a2[4][4];
                    #pragma unroll
                    for (int mt = 0; mt < 4; mt++) ldmx4(a2[mt], aL + (uint32_t)mt * (16 * ROWB) + sw);
                    #pragma unroll
                    for (int mt = 0; mt < 4; mt++)
                        #pragma unroll
                        for (int nt = 0; nt < 8; nt++) {
                            const int g = nt >> 1, s = nt & 1;
                            mma16816h(facc[mt][nt], a2[mt], b1[g][s], b1[g][s + 2]);
                        }
                }
                // term 3 (corr): A1 x B2 -> f16 acc (b2 loaded here, dead after)
                {
                    uint32_t b2[4][4];
                    #pragma unroll
                    for (int h = 0; h < 4; h++) ldmx4(b2[h], bL + (uint32_t)h * (16 * ROWB) + sw);
                    #pragma unroll
                    for (int mt = 0; mt < 4; mt++)
                        #pragma unroll
                        for (int nt = 0; nt < 8; nt++) {
                            const int g = nt >> 1, s = nt & 1;
                            mma16816h(facc[mt][nt], a1[mt], b2[g][s], b2[g][s + 2]);
                        }
                }
            }
        }
    }

    // ---------------- epilogue ----------------
    const int r0 = lane >> 2;
    const int c0 = (lane & 3) * 2;

    #pragma unroll
    for (int mt = 0; mt < 4; mt++) {
        #pragma unroll
        for (int half_ = 0; half_ < 2; half_++) {
            const size_t grow = (size_t)(bm + wm + mt * 16 + r0 + half_ * 8);
            #pragma unroll
            for (int nt = 0; nt < 8; nt++) {
                const int gcol = bn + wn + nt * 8 + c0;
                float v0 = acc[mt][nt][half_ * 2 + 0];
                float v1 = acc[mt][nt][half_ * 2 + 1];
                if (MODE != 3) {
                    // merge f16 correction accumulator
                    __half2 h2 = *reinterpret_cast<__half2*>(&facc[mt][nt][half_]);
                    v0 += __half2float(__low2half(h2));
                    v1 += __half2float(__high2half(h2));
                }

                if (MODE == 1) {
                    v0 += bias[gcol];
                    v1 += bias[gcol + 1];
                    __half h0, l0, h1, l1;
                    split2h(v0, h0, l0); split2h(v1, h1, l1);
                    uint32_t ph = ((uint32_t)__half_as_ushort(h1) << 16) | __half_as_ushort(h0);
                    uint32_t pl = ((uint32_t)__half_as_ushort(l1) << 16) | __half_as_ushort(l0);
                    *(uint32_t*)(Ch + (size_t)bz * sC + grow * N + gcol) = ph;
                    *(uint32_t*)(Cl + (size_t)bz * sC + grow * N + gcol) = pl;
                } else if (MODE == 2) {
                    int2 mm = *(const int2*)(mask + (size_t)bz * sC + grow * N + gcol);
                    float2 vv;
                    vv.x = v0 + (mm.x ? 0.0f : NEGV);
                    vv.y = v1 + (mm.y ? 0.0f : NEGV);
                    *(float2*)(Cf + (size_t)bz * sC + grow * N + gcol) = vv;
                } else {
                    *(float2*)(Cf + (size_t)bz * sC + grow * N + gcol) = make_float2(v0, v1);
                }
            }
        }
    }
}

// ------------------------- elementwise split fp32 -> (hi,lo) fp16 -------------------------
__global__ __launch_bounds__(256)
void split_kernel(const float* __restrict__ x, __half* __restrict__ hi,
                  __half* __restrict__ lo, size_t n)
{
    size_t i = ((size_t)blockIdx.x * 256 + threadIdx.x) * 4;
    if (i >= n) return;
    float4 v = *(const float4*)(x + i);
    float f[4] = {v.x, v.y, v.z, v.w};
    uint32_t ph[2], pl[2];
    #pragma unroll
    for (int j = 0; j < 2; j++) {
        __half h0, l0, h1, l1;
        split2h(f[2*j], h0, l0); split2h(f[2*j+1], h1, l1);
        ph[j] = ((uint32_t)__half_as_ushort(h1) << 16) | __half_as_ushort(h0);
        pl[j] = ((uint32_t)__half_as_ushort(l1) << 16) | __half_as_ushort(l0);
    }
    *(uint2*)(hi + i) = make_uint2(ph[0], ph[1]);
    *(uint2*)(lo + i) = make_uint2(pl[0], pl[1]);
}

// ---- fused: memories fp32 -> split-fp16 row-major (mh,ml) AND single-fp16 transposed ----
__global__ __launch_bounds__(256)
void mem_prep_kernel(const float* __restrict__ src,
                     __half* __restrict__ mh, __half* __restrict__ ml,
                     __half* __restrict__ th,
                     int R, int C)
{
    __shared__ float t[32][33];
    const int z = blockIdx.z;
    src += (size_t)z * R * C;
    mh  += (size_t)z * R * C;  ml += (size_t)z * R * C;
    th  += (size_t)z * R * C;
    const int c0 = blockIdx.x * 32, r0 = blockIdx.y * 32;
    const int tx = threadIdx.x, ty = threadIdx.y;

    #pragma unroll
    for (int i = 0; i < 4; i++) {
        const int r = r0 + ty + 8*i;
        float v = src[(size_t)r * C + c0 + tx];
        t[ty + 8*i][tx] = v;
        __half h, l;
        split2h(v, h, l);
        mh[(size_t)r * C + c0 + tx] = h;
        ml[(size_t)r * C + c0 + tx] = l;
    }
    __syncthreads();
    #pragma unroll
    for (int i = 0; i < 4; i++) {
        const int c = c0 + ty + 8*i;
        float v = t[tx][ty + 8*i];
        th[(size_t)c * R + r0 + tx] = __float2half_rn(v);
    }
}

// ------------------------- row softmax over LM, writes single-fp16 weights -------------------------
__global__ __launch_bounds__(256)
void softmax_kernel(const float* __restrict__ x, __half* __restrict__ w)
{
    const float* row = x + (size_t)blockIdx.x * LM;
    __half* rw = w + (size_t)blockIdx.x * LM;
    const int t = threadIdx.x;
    __shared__ float smax[8], ssum[8];

    float v[8];
    float m = -3.0e38f;
    #pragma unroll
    for (int i = 0; i < 8; i++) { v[i] = row[t + i*256]; m = fmaxf(m, v[i]); }
    #pragma unroll
    for (int o = 16; o > 0; o >>= 1) m = fmaxf(m, __shfl_xor_sync(0xFFFFFFFFu, m, o));
    if ((t & 31) == 0) smax[t >> 5] = m;
    __syncthreads();
    m = smax[0];
    #pragma unroll
    for (int i = 1; i < 8; i++) m = fmaxf(m, smax[i]);

    float s = 0.0f;
    #pragma unroll
    for (int i = 0; i < 8; i++) { v[i] = expf(v[i] - m); s += v[i]; }
    #pragma unroll
    for (int o = 16; o > 0; o >>= 1) s += __shfl_xor_sync(0xFFFFFFFFu, s, o);
    if ((t & 31) == 0) ssum[t >> 5] = s;
    __syncthreads();
    s = 0.0f;
    #pragma unroll
    for (int i = 0; i < 8; i++) s += ssum[i];
    const float inv = 1.0f / s;

    #pragma unroll
    for (int i = 0; i < 8; i++)
        rw[t + i*256] = __float2half_rn(v[i] * inv);
}

// ------------------------- launch -------------------------
extern "C" void kernel_launch(void* const* d_in, const int* in_sizes, int n_in,
                              void* d_out, int out_size)
{
    (void)in_sizes; (void)n_in; (void)out_size;
    const float* query    = (const float*)d_in[0];
    const float* memories = (const float*)d_in[1];
    const int*   mask     = (const int*)d_in[2];
    const float* W        = (const float*)d_in[3];
    const float* bvec     = (const float*)d_in[4];
    float*       out      = (float*)d_out;

    __half *qryh, *qryl, *Wh, *Wl, *qh, *ql, *mh, *ml, *mTh, *w;
    float *logits;
    cudaGetSymbolAddress((void**)&qryh, g_qryh);  cudaGetSymbolAddress((void**)&qryl, g_qryl);
    cudaGetSymbolAddress((void**)&Wh,   g_Wh);    cudaGetSymbolAddress((void**)&Wl,   g_Wl);
    cudaGetSymbolAddress((void**)&qh,   g_qh);    cudaGetSymbolAddress((void**)&ql,   g_ql);
    cudaGetSymbolAddress((void**)&mh,   g_mh);    cudaGetSymbolAddress((void**)&ml,   g_ml);
    cudaGetSymbolAddress((void**)&mTh,  g_mTh);
    cudaGetSymbolAddress((void**)&w,    g_w);
    cudaGetSymbolAddress((void**)&logits, g_logits);

    const int SMEM = NSTAGE * STAGEB;   // 196608 B
    cudaFuncSetAttribute(gemm_mma<1>, cudaFuncAttributeMaxDynamicSharedMemorySize, SMEM);
    cudaFuncSetAttribute(gemm_mma<2>, cudaFuncAttributeMaxDynamicSharedMemorySize, SMEM);
    cudaFuncSetAttribute(gemm_mma<3>, cudaFuncAttributeMaxDynamicSharedMemorySize, SMEM);

    const size_t nQ = (size_t)BB * LQ * DD;
    const size_t nW = (size_t)DD * DD;

    // 0) prep: split query + W; memories -> row-major split (mh,ml) + transposed single (mTh)
    split_kernel<<<(unsigned)(nQ / 1024), 256>>>(query, qryh, qryl, nQ);
    split_kernel<<<(unsigned)(nW / 1024), 256>>>(W,     Wh,   Wl,   nW);
    mem_prep_kernel<<<dim3(DD/32, LM/32, BB), dim3(32, 8)>>>(memories, mh, ml, mTh, LM, DD);

    // 1) q = query @ W^T + b  (main fp32-acc + f16-acc corrections) -> split fp16 (qh, ql)
    gemm_mma<1><<<dim3(DD/256, (BB*LQ)/128, 1), 256, SMEM>>>(
        qryh, qryl, Wh, Wl, bvec, nullptr, nullptr, qh, ql,
        DD, DD, (size_t)0, (size_t)0, (size_t)0);

    // 2) logits = (qh+ql) @ (mh+ml)^T + mask  (main fp32-acc + f16-acc corrections) -> fp32
    gemm_mma<2><<<dim3(LM/256, LQ/128, BB), 256, SMEM>>>(
        qh, ql, mh, ml, nullptr, mask, logits, nullptr, nullptr,
        LM, DD, (size_t)LQ*DD, (size_t)LM*DD, (size_t)LQ*LM);

    // 3) softmax -> single fp16 weights
    softmax_kernel<<<BB*LQ, 256>>>(logits, w);

    // 4) out = w @ mTh^T  (1-term) -> fp32
    gemm_mma<3><<<dim3(DD/256, LQ/128, BB), 256, SMEM>>>(
        w, nullptr, mTh, nullptr, nullptr, nullptr, out, nullptr, nullptr,
        DD, LM, (size_t)LQ*LM, (size_t)DD*LM, (size_t)LQ*DD);
}